// round 11
// baseline (speedup 1.0000x reference)
#include <cuda_runtime.h>
#include <cuda_fp16.h>
#include <math.h>
#include <stdint.h>

#define DIMM   2048
#define NHEADS 16
#define HDIM   128
#define SEQL   1024
#define BS     2
#define ALEN   10
#define MAXF   10
#define KCAT   1152   /* 10 adapter + 1024 keys + 118 zero pad = 9*128 */
#define MPAD   (BS*SEQL + 128)   /* 2176: x rows + adapter row tile */

// ---------------- scratch (device globals; no allocation allowed) ----------
__device__ float  g_QKV[3*MPAD*DIMM];        // fp32 Q|K|V slices (2176 rows each)
__device__ float  g_S [BS*NHEADS*SEQL*KCAT];
__device__ __half g_xh [MPAD*DIMM];          // x (2048) | adapter (10) | zeros
__device__ __half g_wh [3*DIMM*DIMM];        // wq|wk|wv fp16 contiguous
__device__ __half g_woh[DIMM*DIMM];
__device__ __half g_Qh [BS*SEQL*DIMM];
__device__ __half g_Kch[BS*NHEADS*KCAT*HDIM];
__device__ __half g_Vth[BS*NHEADS*HDIM*KCAT];   // V transposed: [z][d][k]
__device__ __half g_Ph [BS*NHEADS*SEQL*KCAT];
__device__ __half g_Oh [BS*SEQL*DIMM];

// ---------------- PTX helpers ----------------------------------------------
__device__ __forceinline__ uint32_t smem_to_u32(const void* p) {
    uint32_t a;
    asm("{ .reg .u64 t; cvta.to.shared.u64 t, %1; cvt.u32.u64 %0, t; }" : "=r"(a) : "l"(p));
    return a;
}
#define CP16(dst, src) \
    asm volatile("cp.async.cg.shared.global [%0], [%1], 16;" :: "r"(dst), "l"(src))
#define CP_COMMIT() asm volatile("cp.async.commit_group;" ::: "memory")
#define CP_WAIT1()  asm volatile("cp.async.wait_group 1;" ::: "memory")

#define LDSM4(r, a) \
    asm volatile("ldmatrix.sync.aligned.m8n8.x4.shared.b16 {%0,%1,%2,%3},[%4];" \
        : "=r"((r)[0]), "=r"((r)[1]), "=r"((r)[2]), "=r"((r)[3]) : "r"(a))

__device__ __forceinline__ void mma16(float* c, const uint32_t* a, uint32_t b0, uint32_t b1) {
    asm volatile(
        "mma.sync.aligned.m16n8k16.row.col.f32.f16.f16.f32 "
        "{%0,%1,%2,%3},{%4,%5,%6,%7},{%8,%9},{%0,%1,%2,%3};"
        : "+f"(c[0]), "+f"(c[1]), "+f"(c[2]), "+f"(c[3])
        : "r"(a[0]), "r"(a[1]), "r"(a[2]), "r"(a[3]), "r"(b0), "r"(b1));
}

// ---------------- fp16 tensor-core batched GEMM: C = A @ B^T ----------------
// CTA tile 128x128, 8 warps (2m x 4n), warp tile 64x32, BK=64, 3-stage cp.async.
// A: (M,K) half row-major, B: (N,K) half row-major. M,N %128==0, K %64==0 (K>=128).
// smem rows 144B pitch (128B data + 16B pad, odd 16B multiple) -> conflict-free.
#define HG_PITCH  144
#define HG_ABYTES (128*HG_PITCH)     /* 18432 */
#define HG_STAGE  (2*HG_ABYTES)      /* 36864 */
#define HG_SMEM   (3*HG_STAGE)       /* 110592 */

template <typename OutT, bool CAUSAL, bool TRUNC>
__global__ __launch_bounds__(256, 2) void hgemm(
    const __half* __restrict__ A, const __half* __restrict__ B, OutT* __restrict__ C,
    int K, int lda, int ldb, int ldc,
    long long aSb, long long aSh, long long bSb, long long bSh,
    long long cSb, long long cSh, int nh)
{
    const int m0 = blockIdx.y * 128, n0 = blockIdx.x * 128;
    if (CAUSAL && n0 > m0 + 127 + ALEN) return;   // fully-masked score tile

    extern __shared__ char smem[];
    const uint32_t sb = smem_to_u32(smem);
    int zb = blockIdx.z / nh, zh = blockIdx.z % nh;
    A += zb*aSb + zh*aSh;
    B += zb*bSb + zh*bSh;
    C += zb*cSb + zh*cSh;

    const int tid = threadIdx.x, lane = tid & 31, warp = tid >> 5;
    const int wm = warp & 1, wn = warp >> 1;       // warp tile 64(m) x 32(n)

    const int Keff = TRUNC ? min(K, (m0 + 128 + ALEN + 63) & ~63) : K;
    const int nch = Keff >> 6;                     // >= 2 for all our shapes

    // copy mapping: 2 threads per row; each thread 4x16B within its 64B half-row
    const int crow = tid >> 1;
    const int chf  = tid & 1;                      // which 64B half of the 128B row
    const __half* ag = A + (long long)(m0 + crow) * lda + chf * 32;
    const __half* bg = B + (long long)(n0 + crow) * ldb + chf * 32;
    const uint32_t sa  = sb + crow*HG_PITCH + chf*64;
    const uint32_t sbb = sb + HG_ABYTES + crow*HG_PITCH + chf*64;

    float acc[4][4][4];
    #pragma unroll
    for (int mi = 0; mi < 4; mi++)
        #pragma unroll
        for (int ni = 0; ni < 4; ni++)
            #pragma unroll
            for (int j = 0; j < 4; j++) acc[mi][ni][j] = 0.f;

    // prologue: stages 0..1 (chunks 0,1)
    #pragma unroll
    for (int s = 0; s < 2; s++) {
        #pragma unroll
        for (int i = 0; i < 4; i++) {
            CP16(sa  + s*HG_STAGE + i*16, ag + s*64 + i*8);
            CP16(sbb + s*HG_STAGE + i*16, bg + s*64 + i*8);
        }
        CP_COMMIT();
    }

    const int rsel = lane & 15, csel = lane >> 4;

    int stage = 0;
    for (int c = 0; c < nch; c++) {
        CP_WAIT1();
        __syncthreads();

        const uint32_t abase = sb + stage*HG_STAGE + (wm*64)*HG_PITCH;
        const uint32_t bbase = sb + stage*HG_STAGE + HG_ABYTES + (wn*32)*HG_PITCH;

        #pragma unroll
        for (int kk = 0; kk < 2; kk++) {
            const int kb = kk * 64;               // byte offset of this k32 pair
            uint32_t a[4][4], b[2][2][4];
            #pragma unroll
            for (int nj = 0; nj < 2; nj++)
                LDSM4(b[0][nj], bbase + (nj*16 + rsel)*HG_PITCH + kb + csel*16);
            #pragma unroll
            for (int nj = 0; nj < 2; nj++)
                LDSM4(b[1][nj], bbase + (nj*16 + rsel)*HG_PITCH + kb + 32 + csel*16);
            #pragma unroll
            for (int mi = 0; mi < 4; mi++)
                LDSM4(a[mi], abase + (mi*16 + rsel)*HG_PITCH + kb + csel*16);

            if (kk == 0) {
                int nxt = c + 2;
                if (nxt < nch) {
                    int s2 = stage + 2; if (s2 >= 3) s2 -= 3;
                    #pragma unroll
                    for (int i = 0; i < 4; i++) {
                        CP16(sa  + s2*HG_STAGE + i*16, ag + nxt*64 + i*8);
                        CP16(sbb + s2*HG_STAGE + i*16, bg + nxt*64 + i*8);
                    }
                }
                CP_COMMIT();
            }

            // ks = 2*kk
            #pragma unroll
            for (int mi = 0; mi < 4; mi++)
                #pragma unroll
                for (int ni = 0; ni < 4; ni++)
                    mma16(acc[mi][ni], a[mi], b[0][ni>>1][ni&1], b[0][ni>>1][(ni&1)+2]);
            // A fragments for ks = 2*kk+1 (reuse regs)
            #pragma unroll
            for (int mi = 0; mi < 4; mi++)
                LDSM4(a[mi], abase + (mi*16 + rsel)*HG_PITCH + kb + 32 + csel*16);
            #pragma unroll
            for (int mi = 0; mi < 4; mi++)
                #pragma unroll
                for (int ni = 0; ni < 4; ni++)
                    mma16(acc[mi][ni], a[mi], b[1][ni>>1][ni&1], b[1][ni>>1][(ni&1)+2]);
        }
        if (++stage == 3) stage = 0;
    }

    const int er = lane >> 2, ec = (lane & 3) * 2;
    #pragma unroll
    for (int mi = 0; mi < 4; mi++) {
        #pragma unroll
        for (int ni = 0; ni < 4; ni++) {
            int row = m0 + wm*64 + mi*16 + er;
            int col = n0 + wn*32 + ni*8 + ec;
            float* cc = acc[mi][ni];
            if (sizeof(OutT) == 4) {
                *(float2*)((float*)C + (long long)row * ldc + col) = make_float2(cc[0], cc[1]);
                *(float2*)((float*)C + (long long)(row+8) * ldc + col) = make_float2(cc[2], cc[3]);
            } else {
                *(__half2*)((__half*)C + (long long)row * ldc + col) = __floats2half2_rn(cc[0], cc[1]);
                *(__half2*)((__half*)C + (long long)(row+8) * ldc + col) = __floats2half2_rn(cc[2], cc[3]);
            }
        }
    }
}

// ---------------- fp32 -> fp16 conversion, 4 float4 per thread (MLP=4) ------
__global__ void f2h_kernel(const float* __restrict__ in, __half* __restrict__ out) {
    int base = blockIdx.x * 1024 + threadIdx.x;
    float4 v[4];
    #pragma unroll
    for (int j = 0; j < 4; j++) v[j] = ((const float4*)in)[base + j*256];
    #pragma unroll
    for (int j = 0; j < 4; j++) {
        int i = base + j*256;
        ((__half2*)out)[2*i]   = __floats2half2_rn(v[j].x, v[j].y);
        ((__half2*)out)[2*i+1] = __floats2half2_rn(v[j].z, v[j].w);
    }
}

// all 4 weight matrices in one launch; wq/wk/wv into contiguous g_wh
__global__ void f2h4_kernel(const float* __restrict__ w0, const float* __restrict__ w1,
                            const float* __restrict__ w2, const float* __restrict__ w3,
                            __half* __restrict__ wh, __half* __restrict__ woh) {
    const float* in;  __half* out;
    switch (blockIdx.y) {
        case 0: in = w0; out = wh; break;
        case 1: in = w1; out = wh + (long long)DIMM*DIMM; break;
        case 2: in = w2; out = wh + 2LL*DIMM*DIMM; break;
        default: in = w3; out = woh; break;
    }
    int base = blockIdx.x * 1024 + threadIdx.x;
    float4 v[4];
    #pragma unroll
    for (int j = 0; j < 4; j++) v[j] = ((const float4*)in)[base + j*256];
    #pragma unroll
    for (int j = 0; j < 4; j++) {
        int i = base + j*256;
        ((__half2*)out)[2*i]   = __floats2half2_rn(v[j].x, v[j].y);
        ((__half2*)out)[2*i+1] = __floats2half2_rn(v[j].z, v[j].w);
    }
}

// ---------------- adapter rows -> xh rows 2048..2175 (10 real + zero pad) ---
__global__ void adapter_fill_kernel(const float* __restrict__ adp) {
    int i = blockIdx.x * 256 + threadIdx.x;     // over 128*2048/8 = 32768 uint4
    int row = i >> 8;                           // 256 8-half chunks per row
    int c8 = (i & 255) * 8;
    __half h[8];
    if (row < ALEN) {
        #pragma unroll
        for (int j = 0; j < 8; j++) h[j] = __float2half(adp[row*DIMM + c8 + j]);
    } else {
        #pragma unroll
        for (int j = 0; j < 8; j++) h[j] = __float2half(0.f);
    }
    *(uint4*)(g_xh + (long long)(BS*SEQL + row)*DIMM + c8) = *(uint4*)h;
}

// ---------------- RoPE on Q: fp32 in -> fp16 out (2 pairs/thread) -----------
__global__ void rope_q_kernel(const float* __restrict__ Q, __half* __restrict__ Qh,
                              const float* __restrict__ cs, const float* __restrict__ sn)
{
    int idx = blockIdx.x * blockDim.x + threadIdx.x;   // BS*SEQL*NHEADS*32
    int pp = (idx & 31) * 2;          // pair base: 0,2,..,62
    int h = (idx >> 5) & 15;
    int r = idx >> 9;                 // global row b*1024+q
    int q = r & 1023;
    float2 c2 = *(const float2*)(cs + q*64 + pp);
    float2 s2 = *(const float2*)(sn + q*64 + pp);
    long long base = (long long)r * DIMM + h * HDIM + 2*pp;
    float4 v = *(const float4*)(Q + base);
    __half2 o0 = __floats2half2_rn(v.x*c2.x - v.y*s2.x, v.x*s2.x + v.y*c2.x);
    __half2 o1 = __floats2half2_rn(v.z*c2.y - v.w*s2.y, v.z*s2.y + v.w*c2.y);
    *(__half2*)(Qh + base)     = o0;
    *(__half2*)(Qh + base + 2) = o1;
}

// ---------------- build Kc (rope fused; adapter rows from K slice) ----------
__global__ void build_kc_kernel(const float* __restrict__ K,
                                const float* __restrict__ cs, const float* __restrict__ sn)
{
    int idx = blockIdx.x * blockDim.x + threadIdx.x;   // BS*NHEADS*KCAT*32
    int pp = (idx & 31) * 2;          // pair base
    int rz = idx >> 5;
    int r = rz % KCAT;
    int z = rz / KCAT;
    int b = z >> 4, h = z & 15;
    __half2 o0 = __floats2half2_rn(0.f, 0.f), o1 = o0;
    if (r < ALEN) {
        float4 v = *(const float4*)(K + (long long)(BS*SEQL + r)*DIMM + h*HDIM + 2*pp);
        o0 = __floats2half2_rn(v.x, v.y);
        o1 = __floats2half2_rn(v.z, v.w);
    } else if (r < ALEN + SEQL) {
        int q = r - ALEN;
        float2 c2 = *(const float2*)(cs + q*64 + pp);
        float2 s2 = *(const float2*)(sn + q*64 + pp);
        float4 v = *(const float4*)(K + (long long)(b*SEQL + q)*DIMM + h*HDIM + 2*pp);
        o0 = __floats2half2_rn(v.x*c2.x - v.y*s2.x, v.x*s2.x + v.y*c2.x);
        o1 = __floats2half2_rn(v.z*c2.y - v.w*s2.y, v.z*s2.y + v.w*c2.y);
    }
    __half* dst = g_Kch + (long long)z*KCAT*HDIM + r*HDIM + 2*pp;
    *(__half2*)dst = o0;
    *(__half2*)(dst + 2) = o1;
}

// ---------------- transposed [adapter|values|pad] V -> fp16 g_Vth[z][d][k] --
__global__ void transpose_v_kernel(const float* __restrict__ V)
{
    __shared__ float tile[32][33];
    int z = blockIdx.z;
    int b = z >> 4, h = z & 15;
    int kt = blockIdx.x * 32, dt = blockIdx.y * 32;
    int tx = threadIdx.x, ty = threadIdx.y;   // 32 x 8
    #pragma unroll
    for (int j = 0; j < 4; j++) {
        int k = kt + ty + 8*j;
        int d = dt + tx;
        float v = 0.f;
        if (k < ALEN) v = V[(long long)(BS*SEQL + k)*DIMM + h*HDIM + d];
        else if (k < ALEN + SEQL)
            v = V[((long long)(b * SEQL + k - ALEN)) * DIMM + h * HDIM + d];
        tile[ty + 8*j][tx] = v;
    }
    __syncthreads();
    #pragma unroll
    for (int j = 0; j < 4; j++) {
        int d = dt + ty + 8*j;
        g_Vth[((long long)z * HDIM + d) * KCAT + kt + tx] = __float2half(tile[tx][ty + 8*j]);
    }
}

// ---------------- softmax: warp per row, shfl-only reductions ---------------
__global__ __launch_bounds__(256) void softmax_kernel(
    const float* __restrict__ S,
    const float* __restrict__ gate1,
    const float* __restrict__ gate2,
    const int*   __restrict__ vsp)
{
    const int rowid = blockIdx.x * 8 + (threadIdx.x >> 5);   // BS*NHEADS*SEQL rows
    const int lane = threadIdx.x & 31;
    const int z = rowid >> 10, q = rowid & 1023, h = z & 15;
    const float* row = S + (long long)rowid * KCAT;
    __half* hrow = g_Ph + (long long)rowid * KCAT;
    const int vs = *vsp;
    const float scale = 0.08838834764831843f;   // 1/sqrt(128)
    const float g2 = gate2[h];
    const bool grow = (q >= vs + MAXF);

    float e[32];
    float lmax = -1e30f;
    #pragma unroll
    for (int i = 0; i < 32; i++) {
        int k = i*32 + lane;
        float v = -1e30f;
        if (k <= q) {
            v = row[ALEN + k] * scale;
            if (grow && k >= vs && k < vs + MAXF) v += g2;
        }
        e[i] = v;  lmax = fmaxf(lmax, v);
    }
    #pragma unroll
    for (int o = 16; o > 0; o >>= 1) lmax = fmaxf(lmax, __shfl_xor_sync(0xffffffffu, lmax, o));

    float lsum = 0.f;
    #pragma unroll
    for (int i = 0; i < 32; i++) {
        int k = i*32 + lane;
        float x = (k <= q) ? expf(e[i] - lmax) : 0.f;
        e[i] = x;  lsum += x;
    }
    #pragma unroll
    for (int o = 16; o > 0; o >>= 1) lsum += __shfl_xor_sync(0xffffffffu, lsum, o);
    float inv = 1.0f / lsum;

    #pragma unroll
    for (int i = 0; i < 32; i++)
        hrow[ALEN + i*32 + lane] = __float2half(e[i] * inv);
    for (int k = SEQL + lane; k < KCAT - ALEN; k += 32)     // zero pad cols
        hrow[ALEN + k] = __float2half(0.f);

    // adapter segment: separate softmax * tanh(gate1[h])
    float av = (lane < ALEN) ? row[lane] * scale : -1e30f;
    float am = av;
    #pragma unroll
    for (int o = 16; o > 0; o >>= 1) am = fmaxf(am, __shfl_xor_sync(0xffffffffu, am, o));
    float ae = (lane < ALEN) ? expf(av - am) : 0.f;
    float as = ae;
    #pragma unroll
    for (int o = 16; o > 0; o >>= 1) as += __shfl_xor_sync(0xffffffffu, as, o);
    if (lane < ALEN) hrow[lane] = __float2half(ae * tanhf(gate1[h]) / as);
}

// ---------------- launch -----------------------------------------------------
extern "C" void kernel_launch(void* const* d_in, const int* in_sizes, int n_in,
                              void* d_out, int out_size)
{
    const float* x   = (const float*)d_in[0];
    const float* adp = (const float*)d_in[1];
    /* d_in[2] = mask: equivalent to hard causal mask, recomputed on device */
    const float* fc  = (const float*)d_in[3];
    const float* fs  = (const float*)d_in[4];
    const float* wq  = (const float*)d_in[5];
    const float* wk  = (const float*)d_in[6];
    const float* wv  = (const float*)d_in[7];
    const float* wo  = (const float*)d_in[8];
    const float* g1  = (const float*)d_in[9];
    const float* g2  = (const float*)d_in[10];
    const int*   vsp = (const int*)d_in[11];
    float* out = (float*)d_out;

    float *QKVp, *Sp;
    __half *xh, *wh, *woh, *Qhp, *Kchp, *Vthp, *Php, *Ohp;
    cudaGetSymbolAddress((void**)&QKVp, g_QKV);
    cudaGetSymbolAddress((void**)&Sp,  g_S);
    cudaGetSymbolAddress((void**)&xh,  g_xh);
    cudaGetSymbolAddress((void**)&wh,  g_wh);
    cudaGetSymbolAddress((void**)&woh, g_woh);
    cudaGetSymbolAddress((void**)&Qhp, g_Qh);
    cudaGetSymbolAddress((void**)&Kchp, g_Kch);
    cudaGetSymbolAddress((void**)&Vthp, g_Vth);
    cudaGetSymbolAddress((void**)&Php, g_Ph);
    cudaGetSymbolAddress((void**)&Ohp, g_Oh);

    float* Qp = QKVp;
    float* Kp = QKVp + (long long)MPAD*DIMM;
    float* Vp = QKVp + 2LL*MPAD*DIMM;

    cudaFuncSetAttribute((const void*)hgemm<float,false,false>, cudaFuncAttributeMaxDynamicSharedMemorySize, HG_SMEM);
    cudaFuncSetAttribute((const void*)hgemm<float,true,false>,  cudaFuncAttributeMaxDynamicSharedMemorySize, HG_SMEM);
    cudaFuncSetAttribute((const void*)hgemm<__half,false,true>, cudaFuncAttributeMaxDynamicSharedMemorySize, HG_SMEM);

    // fp32 -> fp16 conversions + adapter rows into xh
    f2h_kernel<<<BS*SEQL*DIMM/4096, 256>>>(x, xh);
    f2h4_kernel<<<dim3(DIMM*DIMM/4096, 4), 256>>>(wq, wk, wv, wo, wh, woh);
    adapter_fill_kernel<<<128, 256>>>(adp);

    // QKV projections fused (M=2176 incl. adapter rows); z selects weight/output
    hgemm<float,false,false><<<dim3(DIMM/128, MPAD/128, 3), 256, HG_SMEM>>>(
        xh, wh, QKVp, DIMM, DIMM, DIMM, DIMM,
        0, 0, 0, (long long)DIMM*DIMM,
        0, (long long)MPAD*DIMM, 3);

    rope_q_kernel<<<BS*SEQL*NHEADS*32/256, 256>>>(Qp, Qhp, fc, fs);
    build_kc_kernel<<<(BS*NHEADS*KCAT*32)/256, 256>>>(Kp, fc, fs);
    transpose_v_kernel<<<dim3(KCAT/32, HDIM/32, BS*NHEADS), dim3(32, 8)>>>(Vp);

    // scores: per z: S(1024x1152) = Qh(1024x128) @ Kch^T  (causal tile skip)
    hgemm<float,true,false><<<dim3(KCAT/128, SEQL/128, BS*NHEADS), 256, HG_SMEM>>>(
        Qhp, Kchp, Sp, HDIM,
        DIMM, HDIM, KCAT,
        (long long)SEQL*DIMM, (long long)HDIM,
        (long long)NHEADS*KCAT*HDIM, (long long)KCAT*HDIM,
        (long long)NHEADS*SEQL*KCAT, (long long)SEQL*KCAT, NHEADS);

    softmax_kernel<<<BS*NHEADS*SEQL/8, 256>>>(Sp, g1, g2, vsp);

    // attn: per z: Oh(1024x128) = Ph(1024x1152) @ Vth(128x1152)^T  (K-truncated)
    hgemm<__half,false,true><<<dim3(1, SEQL/128, BS*NHEADS), 256, HG_SMEM>>>(
        Php, Vthp, Ohp, KCAT,
        KCAT, KCAT, DIMM,
        (long long)NHEADS*SEQL*KCAT, (long long)SEQL*KCAT,
        (long long)NHEADS*HDIM*KCAT, (long long)HDIM*KCAT,
        (long long)SEQL*DIMM, (long long)HDIM, NHEADS);

    // output projection: fp32 out to d_out
    hgemm<float,false,false><<<dim3(DIMM/128, (BS*SEQL)/128, 1), 256, HG_SMEM>>>(
        Ohp, woh, out, DIMM, DIMM, DIMM, DIMM, 0,0,0,0,0,0, 1);
}

// round 12
// speedup vs baseline: 1.1726x; 1.1726x over previous
#include <cuda_runtime.h>
#include <cuda_fp16.h>
#include <math.h>
#include <stdint.h>

#define DIMM   2048
#define NHEADS 16
#define HDIM   128
#define SEQL   1024
#define BS     2
#define ALEN   10
#define MAXF   10
#define KCAT   1152   /* 10 adapter + 1024 keys + 118 zero pad = 9*128 */
#define MPAD   (BS*SEQL + 128)   /* 2176: x rows + adapter row tile */

// ---------------- scratch (device globals; no allocation allowed) ----------
__device__ float  g_QKV[3*MPAD*DIMM];        // fp32 Q|K|V slices (2176 rows each)
__device__ float  g_S [BS*NHEADS*SEQL*KCAT];
__device__ __half g_xh [MPAD*DIMM];          // x (2048) | adapter (10) | zeros
__device__ __half g_wh [3*DIMM*DIMM];        // wq|wk|wv fp16 contiguous
__device__ __half g_woh[DIMM*DIMM];
__device__ __half g_Qh [BS*SEQL*DIMM];
__device__ __half g_Kch[BS*NHEADS*KCAT*HDIM];
__device__ __half g_Vth[BS*NHEADS*HDIM*KCAT];   // V transposed: [z][d][k]
__device__ __half g_Ph [BS*NHEADS*SEQL*KCAT];
__device__ __half g_Oh [BS*SEQL*DIMM];

// ---------------- PTX helpers ----------------------------------------------
__device__ __forceinline__ uint32_t smem_to_u32(const void* p) {
    uint32_t a;
    asm("{ .reg .u64 t; cvta.to.shared.u64 t, %1; cvt.u32.u64 %0, t; }" : "=r"(a) : "l"(p));
    return a;
}
#define CP16(dst, src) \
    asm volatile("cp.async.cg.shared.global [%0], [%1], 16;" :: "r"(dst), "l"(src))
#define CP_COMMIT() asm volatile("cp.async.commit_group;" ::: "memory")
#define CP_WAIT2()  asm volatile("cp.async.wait_group 2;" ::: "memory")

#define LDSM4(r, a) \
    asm volatile("ldmatrix.sync.aligned.m8n8.x4.shared.b16 {%0,%1,%2,%3},[%4];" \
        : "=r"((r)[0]), "=r"((r)[1]), "=r"((r)[2]), "=r"((r)[3]) : "r"(a))

__device__ __forceinline__ void mma16(float* c, const uint32_t* a, uint32_t b0, uint32_t b1) {
    asm volatile(
        "mma.sync.aligned.m16n8k16.row.col.f32.f16.f16.f32 "
        "{%0,%1,%2,%3},{%4,%5,%6,%7},{%8,%9},{%0,%1,%2,%3};"
        : "+f"(c[0]), "+f"(c[1]), "+f"(c[2]), "+f"(c[3])
        : "r"(a[0]), "r"(a[1]), "r"(a[2]), "r"(a[3]), "r"(b0), "r"(b1));
}

// ---------------- fp16 tensor-core batched GEMM: C = A @ B^T ----------------
// CTA tile 128x128, 8 warps (2m x 4n), warp tile 64x32, BK=32, 4-stage cp.async.
// A: (M,K) half row-major, B: (N,K) half row-major. M,N %128==0, K %32==0.
// smem rows 80B pitch (64B data + 16B pad) -> conflict-free ldmatrix.
#define HG_STAGE 20480
#define HG_SMEM  81920

template <typename OutT, bool CAUSAL, bool TRUNC>
__global__ __launch_bounds__(256, 2) void hgemm(
    const __half* __restrict__ A, const __half* __restrict__ B, OutT* __restrict__ C,
    int K, int lda, int ldb, int ldc,
    long long aSb, long long aSh, long long bSb, long long bSh,
    long long cSb, long long cSh, int nh)
{
    const int m0 = blockIdx.y * 128, n0 = blockIdx.x * 128;
    if (CAUSAL && n0 > m0 + 127 + ALEN) return;   // fully-masked score tile

    extern __shared__ char smem[];
    const uint32_t sb = smem_to_u32(smem);
    int zb = blockIdx.z / nh, zh = blockIdx.z % nh;
    A += zb*aSb + zh*aSh;
    B += zb*bSb + zh*bSh;
    C += zb*cSb + zh*cSh;

    const int tid = threadIdx.x, lane = tid & 31, warp = tid >> 5;
    const int wm = warp & 1, wn = warp >> 1;       // warp tile 64(m) x 32(n)

    const int Keff = TRUNC ? min(K, (m0 + 128 + ALEN + 31) & ~31) : K;
    const int nch = Keff >> 5;                     // >= 4 for all our shapes

    // copy mapping: thread -> row tid>>1, two 16B segs at (tid&1)*32 bytes
    const int crow = tid >> 1;
    const int cseg = (tid & 1) * 2;
    const __half* ag = A + (long long)(m0 + crow) * lda + cseg * 8;
    const __half* bg = B + (long long)(n0 + crow) * ldb + cseg * 8;
    const uint32_t sa = sb + crow*80 + cseg*16;
    const uint32_t sbb = sb + 10240 + crow*80 + cseg*16;

    float acc[4][4][4];
    #pragma unroll
    for (int mi = 0; mi < 4; mi++)
        #pragma unroll
        for (int ni = 0; ni < 4; ni++)
            #pragma unroll
            for (int j = 0; j < 4; j++) acc[mi][ni][j] = 0.f;

    // prologue: stages 0..2
    #pragma unroll
    for (int s = 0; s < 3; s++) {
        CP16(sa  + s*HG_STAGE,      ag + s*32);
        CP16(sa  + s*HG_STAGE + 16, ag + s*32 + 8);
        CP16(sbb + s*HG_STAGE,      bg + s*32);
        CP16(sbb + s*HG_STAGE + 16, bg + s*32 + 8);
        CP_COMMIT();
    }

    const int rsel = lane & 15, csel = lane >> 4;

    for (int c = 0; c < nch; c++) {
        CP_WAIT2();
        __syncthreads();

        const uint32_t abase = sb + (c & 3)*HG_STAGE + (wm*64)*80;
        const uint32_t bbase = sb + (c & 3)*HG_STAGE + 10240 + (wn*32)*80;

        uint32_t a[4][4], b[2][2][4];
        // hoist B fragments for both ks-steps + A for ks0
        #pragma unroll
        for (int nj = 0; nj < 2; nj++)
            LDSM4(b[0][nj], bbase + (nj*16 + rsel)*80 + csel*16);
        #pragma unroll
        for (int nj = 0; nj < 2; nj++)
            LDSM4(b[1][nj], bbase + (nj*16 + rsel)*80 + 32 + csel*16);
        #pragma unroll
        for (int mi = 0; mi < 4; mi++)
            LDSM4(a[mi], abase + (mi*16 + rsel)*80 + csel*16);

        // issue next-chunk copies under the fragment loads
        int nxt = c + 3;
        if (nxt < nch) {
            int s = nxt & 3;
            CP16(sa  + s*HG_STAGE,      ag + nxt*32);
            CP16(sa  + s*HG_STAGE + 16, ag + nxt*32 + 8);
            CP16(sbb + s*HG_STAGE,      bg + nxt*32);
            CP16(sbb + s*HG_STAGE + 16, bg + nxt*32 + 8);
        }
        CP_COMMIT();

        // ks = 0, each mi's MMAs followed by that mi's ks1 A reload
        // (LDSM latency hides behind the next mi's MMA burst)
        #pragma unroll
        for (int mi = 0; mi < 4; mi++) {
            #pragma unroll
            for (int ni = 0; ni < 4; ni++)
                mma16(acc[mi][ni], a[mi], b[0][ni>>1][ni&1], b[0][ni>>1][(ni&1)+2]);
            LDSM4(a[mi], abase + (mi*16 + rsel)*80 + 32 + csel*16);
        }
        // ks = 1
        #pragma unroll
        for (int mi = 0; mi < 4; mi++)
            #pragma unroll
            for (int ni = 0; ni < 4; ni++)
                mma16(acc[mi][ni], a[mi], b[1][ni>>1][ni&1], b[1][ni>>1][(ni&1)+2]);
    }

    const int er = lane >> 2, ec = (lane & 3) * 2;
    #pragma unroll
    for (int mi = 0; mi < 4; mi++) {
        #pragma unroll
        for (int ni = 0; ni < 4; ni++) {
            int row = m0 + wm*64 + mi*16 + er;
            int col = n0 + wn*32 + ni*8 + ec;
            float* cc = acc[mi][ni];
            if (sizeof(OutT) == 4) {
                *(float2*)((float*)C + (long long)row * ldc + col) = make_float2(cc[0], cc[1]);
                *(float2*)((float*)C + (long long)(row+8) * ldc + col) = make_float2(cc[2], cc[3]);
            } else {
                *(__half2*)((__half*)C + (long long)row * ldc + col) = __floats2half2_rn(cc[0], cc[1]);
                *(__half2*)((__half*)C + (long long)(row+8) * ldc + col) = __floats2half2_rn(cc[2], cc[3]);
            }
        }
    }
}

// ---------------- fp32 -> fp16 conversion, 4 float4 per thread (MLP=4) ------
__global__ void f2h_kernel(const float* __restrict__ in, __half* __restrict__ out) {
    int base = blockIdx.x * 1024 + threadIdx.x;
    float4 v[4];
    #pragma unroll
    for (int j = 0; j < 4; j++) v[j] = ((const float4*)in)[base + j*256];
    #pragma unroll
    for (int j = 0; j < 4; j++) {
        int i = base + j*256;
        ((__half2*)out)[2*i]   = __floats2half2_rn(v[j].x, v[j].y);
        ((__half2*)out)[2*i+1] = __floats2half2_rn(v[j].z, v[j].w);
    }
}

// all 4 weight matrices in one launch; wq/wk/wv into contiguous g_wh
__global__ void f2h4_kernel(const float* __restrict__ w0, const float* __restrict__ w1,
                            const float* __restrict__ w2, const float* __restrict__ w3,
                            __half* __restrict__ wh, __half* __restrict__ woh) {
    const float* in;  __half* out;
    switch (blockIdx.y) {
        case 0: in = w0; out = wh; break;
        case 1: in = w1; out = wh + (long long)DIMM*DIMM; break;
        case 2: in = w2; out = wh + 2LL*DIMM*DIMM; break;
        default: in = w3; out = woh; break;
    }
    int base = blockIdx.x * 1024 + threadIdx.x;
    float4 v[4];
    #pragma unroll
    for (int j = 0; j < 4; j++) v[j] = ((const float4*)in)[base + j*256];
    #pragma unroll
    for (int j = 0; j < 4; j++) {
        int i = base + j*256;
        ((__half2*)out)[2*i]   = __floats2half2_rn(v[j].x, v[j].y);
        ((__half2*)out)[2*i+1] = __floats2half2_rn(v[j].z, v[j].w);
    }
}

// ---------------- adapter rows -> xh rows 2048..2175 (10 real + zero pad) ---
__global__ void adapter_fill_kernel(const float* __restrict__ adp) {
    int i = blockIdx.x * 256 + threadIdx.x;     // over 128*2048/8 = 32768 uint4
    int row = i >> 8;                           // 256 8-half chunks per row
    int c8 = (i & 255) * 8;
    __half h[8];
    if (row < ALEN) {
        #pragma unroll
        for (int j = 0; j < 8; j++) h[j] = __float2half(adp[row*DIMM + c8 + j]);
    } else {
        #pragma unroll
        for (int j = 0; j < 8; j++) h[j] = __float2half(0.f);
    }
    *(uint4*)(g_xh + (long long)(BS*SEQL + row)*DIMM + c8) = *(uint4*)h;
}

// ---------------- RoPE on Q: fp32 in -> fp16 out (2 pairs/thread) -----------
__global__ void rope_q_kernel(const float* __restrict__ Q, __half* __restrict__ Qh,
                              const float* __restrict__ cs, const float* __restrict__ sn)
{
    int idx = blockIdx.x * blockDim.x + threadIdx.x;   // BS*SEQL*NHEADS*32
    int pp = (idx & 31) * 2;          // pair base: 0,2,..,62
    int h = (idx >> 5) & 15;
    int r = idx >> 9;                 // global row b*1024+q
    int q = r & 1023;
    float2 c2 = *(const float2*)(cs + q*64 + pp);
    float2 s2 = *(const float2*)(sn + q*64 + pp);
    long long base = (long long)r * DIMM + h * HDIM + 2*pp;
    float4 v = *(const float4*)(Q + base);
    __half2 o0 = __floats2half2_rn(v.x*c2.x - v.y*s2.x, v.x*s2.x + v.y*c2.x);
    __half2 o1 = __floats2half2_rn(v.z*c2.y - v.w*s2.y, v.z*s2.y + v.w*c2.y);
    *(__half2*)(Qh + base)     = o0;
    *(__half2*)(Qh + base + 2) = o1;
}

// ---------------- build Kc (rope fused; adapter rows from K slice) ----------
__global__ void build_kc_kernel(const float* __restrict__ K,
                                const float* __restrict__ cs, const float* __restrict__ sn)
{
    int idx = blockIdx.x * blockDim.x + threadIdx.x;   // BS*NHEADS*KCAT*32
    int pp = (idx & 31) * 2;          // pair base
    int rz = idx >> 5;
    int r = rz % KCAT;
    int z = rz / KCAT;
    int b = z >> 4, h = z & 15;
    __half2 o0 = __floats2half2_rn(0.f, 0.f), o1 = o0;
    if (r < ALEN) {
        float4 v = *(const float4*)(K + (long long)(BS*SEQL + r)*DIMM + h*HDIM + 2*pp);
        o0 = __floats2half2_rn(v.x, v.y);
        o1 = __floats2half2_rn(v.z, v.w);
    } else if (r < ALEN + SEQL) {
        int q = r - ALEN;
        float2 c2 = *(const float2*)(cs + q*64 + pp);
        float2 s2 = *(const float2*)(sn + q*64 + pp);
        float4 v = *(const float4*)(K + (long long)(b*SEQL + q)*DIMM + h*HDIM + 2*pp);
        o0 = __floats2half2_rn(v.x*c2.x - v.y*s2.x, v.x*s2.x + v.y*c2.x);
        o1 = __floats2half2_rn(v.z*c2.y - v.w*s2.y, v.z*s2.y + v.w*c2.y);
    }
    __half* dst = g_Kch + (long long)z*KCAT*HDIM + r*HDIM + 2*pp;
    *(__half2*)dst = o0;
    *(__half2*)(dst + 2) = o1;
}

// ---------------- transposed [adapter|values|pad] V -> fp16 g_Vth[z][d][k] --
__global__ void transpose_v_kernel(const float* __restrict__ V)
{
    __shared__ float tile[32][33];
    int z = blockIdx.z;
    int b = z >> 4, h = z & 15;
    int kt = blockIdx.x * 32, dt = blockIdx.y * 32;
    int tx = threadIdx.x, ty = threadIdx.y;   // 32 x 8
    #pragma unroll
    for (int j = 0; j < 4; j++) {
        int k = kt + ty + 8*j;
        int d = dt + tx;
        float v = 0.f;
        if (k < ALEN) v = V[(long long)(BS*SEQL + k)*DIMM + h*HDIM + d];
        else if (k < ALEN + SEQL)
            v = V[((long long)(b * SEQL + k - ALEN)) * DIMM + h * HDIM + d];
        tile[ty + 8*j][tx] = v;
    }
    __syncthreads();
    #pragma unroll
    for (int j = 0; j < 4; j++) {
        int d = dt + ty + 8*j;
        g_Vth[((long long)z * HDIM + d) * KCAT + kt + tx] = __float2half(tile[tx][ty + 8*j]);
    }
}

// ---------------- softmax: warp per row, shfl-only reductions ---------------
__global__ __launch_bounds__(256) void softmax_kernel(
    const float* __restrict__ S,
    const float* __restrict__ gate1,
    const float* __restrict__ gate2,
    const int*   __restrict__ vsp)
{
    const int rowid = blockIdx.x * 8 + (threadIdx.x >> 5);   // BS*NHEADS*SEQL rows
    const int lane = threadIdx.x & 31;
    const int z = rowid >> 10, q = rowid & 1023, h = z & 15;
    const float* row = S + (long long)rowid * KCAT;
    __half* hrow = g_Ph + (long long)rowid * KCAT;
    const int vs = *vsp;
    const float scale = 0.08838834764831843f;   // 1/sqrt(128)
    const float g2 = gate2[h];
    const bool grow = (q >= vs + MAXF);

    float e[32];
    float lmax = -1e30f;
    #pragma unroll
    for (int i = 0; i < 32; i++) {
        int k = i*32 + lane;
        float v = -1e30f;
        if (k <= q) {
            v = row[ALEN + k] * scale;
            if (grow && k >= vs && k < vs + MAXF) v += g2;
        }
        e[i] = v;  lmax = fmaxf(lmax, v);
    }
    #pragma unroll
    for (int o = 16; o > 0; o >>= 1) lmax = fmaxf(lmax, __shfl_xor_sync(0xffffffffu, lmax, o));

    float lsum = 0.f;
    #pragma unroll
    for (int i = 0; i < 32; i++) {
        int k = i*32 + lane;
        float x = (k <= q) ? expf(e[i] - lmax) : 0.f;
        e[i] = x;  lsum += x;
    }
    #pragma unroll
    for (int o = 16; o > 0; o >>= 1) lsum += __shfl_xor_sync(0xffffffffu, lsum, o);
    float inv = 1.0f / lsum;

    #pragma unroll
    for (int i = 0; i < 32; i++)
        hrow[ALEN + i*32 + lane] = __float2half(e[i] * inv);
    for (int k = SEQL + lane; k < KCAT - ALEN; k += 32)     // zero pad cols
        hrow[ALEN + k] = __float2half(0.f);

    // adapter segment: separate softmax * tanh(gate1[h])
    float av = (lane < ALEN) ? row[lane] * scale : -1e30f;
    float am = av;
    #pragma unroll
    for (int o = 16; o > 0; o >>= 1) am = fmaxf(am, __shfl_xor_sync(0xffffffffu, am, o));
    float ae = (lane < ALEN) ? expf(av - am) : 0.f;
    float as = ae;
    #pragma unroll
    for (int o = 16; o > 0; o >>= 1) as += __shfl_xor_sync(0xffffffffu, as, o);
    if (lane < ALEN) hrow[lane] = __float2half(ae * tanhf(gate1[h]) / as);
}

// ---------------- launch -----------------------------------------------------
extern "C" void kernel_launch(void* const* d_in, const int* in_sizes, int n_in,
                              void* d_out, int out_size)
{
    const float* x   = (const float*)d_in[0];
    const float* adp = (const float*)d_in[1];
    /* d_in[2] = mask: equivalent to hard causal mask, recomputed on device */
    const float* fc  = (const float*)d_in[3];
    const float* fs  = (const float*)d_in[4];
    const float* wq  = (const float*)d_in[5];
    const float* wk  = (const float*)d_in[6];
    const float* wv  = (const float*)d_in[7];
    const float* wo  = (const float*)d_in[8];
    const float* g1  = (const float*)d_in[9];
    const float* g2  = (const float*)d_in[10];
    const int*   vsp = (const int*)d_in[11];
    float* out = (float*)d_out;

    float *QKVp, *Sp;
    __half *xh, *wh, *woh, *Qhp, *Kchp, *Vthp, *Php, *Ohp;
    cudaGetSymbolAddress((void**)&QKVp, g_QKV);
    cudaGetSymbolAddress((void**)&Sp,  g_S);
    cudaGetSymbolAddress((void**)&xh,  g_xh);
    cudaGetSymbolAddress((void**)&wh,  g_wh);
    cudaGetSymbolAddress((void**)&woh, g_woh);
    cudaGetSymbolAddress((void**)&Qhp, g_Qh);
    cudaGetSymbolAddress((void**)&Kchp, g_Kch);
    cudaGetSymbolAddress((void**)&Vthp, g_Vth);
    cudaGetSymbolAddress((void**)&Php, g_Ph);
    cudaGetSymbolAddress((void**)&Ohp, g_Oh);

    float* Qp = QKVp;
    float* Kp = QKVp + (long long)MPAD*DIMM;
    float* Vp = QKVp + 2LL*MPAD*DIMM;

    cudaFuncSetAttribute((const void*)hgemm<float,false,false>, cudaFuncAttributeMaxDynamicSharedMemorySize, HG_SMEM);
    cudaFuncSetAttribute((const void*)hgemm<float,true,false>,  cudaFuncAttributeMaxDynamicSharedMemorySize, HG_SMEM);
    cudaFuncSetAttribute((const void*)hgemm<__half,false,true>, cudaFuncAttributeMaxDynamicSharedMemorySize, HG_SMEM);

    // fp32 -> fp16 conversions + adapter rows into xh
    f2h_kernel<<<BS*SEQL*DIMM/4096, 256>>>(x, xh);
    f2h4_kernel<<<dim3(DIMM*DIMM/4096, 4), 256>>>(wq, wk, wv, wo, wh, woh);
    adapter_fill_kernel<<<128, 256>>>(adp);

    // QKV projections fused (M=2176 incl. adapter rows); z selects weight/output
    hgemm<float,false,false><<<dim3(DIMM/128, MPAD/128, 3), 256, HG_SMEM>>>(
        xh, wh, QKVp, DIMM, DIMM, DIMM, DIMM,
        0, 0, 0, (long long)DIMM*DIMM,
        0, (long long)MPAD*DIMM, 3);

    rope_q_kernel<<<BS*SEQL*NHEADS*32/256, 256>>>(Qp, Qhp, fc, fs);
    build_kc_kernel<<<(BS*NHEADS*KCAT*32)/256, 256>>>(Kp, fc, fs);
    transpose_v_kernel<<<dim3(KCAT/32, HDIM/32, BS*NHEADS), dim3(32, 8)>>>(Vp);

    // scores: per z: S(1024x1152) = Qh(1024x128) @ Kch^T  (causal tile skip)
    hgemm<float,true,false><<<dim3(KCAT/128, SEQL/128, BS*NHEADS), 256, HG_SMEM>>>(
        Qhp, Kchp, Sp, HDIM,
        DIMM, HDIM, KCAT,
        (long long)SEQL*DIMM, (long long)HDIM,
        (long long)NHEADS*KCAT*HDIM, (long long)KCAT*HDIM,
        (long long)NHEADS*SEQL*KCAT, (long long)SEQL*KCAT, NHEADS);

    softmax_kernel<<<BS*NHEADS*SEQL/8, 256>>>(Sp, g1, g2, vsp);

    // attn: per z: Oh(1024x128) = Ph(1024x1152) @ Vth(128x1152)^T  (K-truncated)
    hgemm<__half,false,true><<<dim3(1, SEQL/128, BS*NHEADS), 256, HG_SMEM>>>(
        Php, Vthp, Ohp, KCAT,
        KCAT, KCAT, DIMM,
        (long long)NHEADS*SEQL*KCAT, (long long)SEQL*KCAT,
        (long long)NHEADS*HDIM*KCAT, (long long)HDIM*KCAT,
        (long long)SEQL*DIMM, (long long)HDIM, NHEADS);

    // output projection: fp32 out to d_out
    hgemm<float,false,false><<<dim3(DIMM/128, (BS*SEQL)/128, 1), 256, HG_SMEM>>>(
        Ohp, woh, out, DIMM, DIMM, DIMM, DIMM, 0,0,0,0,0,0, 1);
}

// round 13
// speedup vs baseline: 1.1733x; 1.0006x over previous
#include <cuda_runtime.h>
#include <cuda_fp16.h>
#include <math.h>
#include <stdint.h>

#define DIMM   2048
#define NHEADS 16
#define HDIM   128
#define SEQL   1024
#define BS     2
#define ALEN   10
#define MAXF   10
#define KCAT   1152   /* 10 adapter + 1024 keys + 118 zero pad = 9*128 */
#define MPAD   (BS*SEQL + 128)   /* 2176: x rows + adapter row tile */

// ---------------- scratch (device globals; no allocation allowed) ----------
__device__ float  g_S [BS*NHEADS*SEQL*KCAT];
__device__ __half g_xh [MPAD*DIMM];          // x (2048) | adapter (10) | zeros
__device__ __half g_wh [3*DIMM*DIMM];        // wq|wk|wv fp16 contiguous
__device__ __half g_woh[DIMM*DIMM];
__device__ __half g_Qh [BS*SEQL*DIMM];
__device__ __half g_Vh [MPAD*DIMM];          // V fp16 (incl. adapter rows)
__device__ __half g_Kch[BS*NHEADS*KCAT*HDIM];
__device__ __half g_Vth[BS*NHEADS*HDIM*KCAT];   // V transposed: [z][d][k]
__device__ __half g_Ph [BS*NHEADS*SEQL*KCAT];
__device__ __half g_Oh [BS*SEQL*DIMM];

// ---------------- PTX helpers ----------------------------------------------
__device__ __forceinline__ uint32_t smem_to_u32(const void* p) {
    uint32_t a;
    asm("{ .reg .u64 t; cvta.to.shared.u64 t, %1; cvt.u32.u64 %0, t; }" : "=r"(a) : "l"(p));
    return a;
}
#define CP16(dst, src) \
    asm volatile("cp.async.cg.shared.global [%0], [%1], 16;" :: "r"(dst), "l"(src))
#define CP_COMMIT() asm volatile("cp.async.commit_group;" ::: "memory")
#define CP_WAIT2()  asm volatile("cp.async.wait_group 2;" ::: "memory")

#define LDSM4(r, a) \
    asm volatile("ldmatrix.sync.aligned.m8n8.x4.shared.b16 {%0,%1,%2,%3},[%4];" \
        : "=r"((r)[0]), "=r"((r)[1]), "=r"((r)[2]), "=r"((r)[3]) : "r"(a))

__device__ __forceinline__ void mma16(float* c, const uint32_t* a, uint32_t b0, uint32_t b1) {
    asm volatile(
        "mma.sync.aligned.m16n8k16.row.col.f32.f16.f16.f32 "
        "{%0,%1,%2,%3},{%4,%5,%6,%7},{%8,%9},{%0,%1,%2,%3};"
        : "+f"(c[0]), "+f"(c[1]), "+f"(c[2]), "+f"(c[3])
        : "r"(a[0]), "r"(a[1]), "r"(a[2]), "r"(a[3]), "r"(b0), "r"(b1));
}

// ---------------- fp16 tensor-core batched GEMM: C = A @ B^T ----------------
// CTA tile 128x128, 8 warps (2m x 4n), warp tile 64x32, BK=32, 4-stage cp.async.
// FUSE mode (QKV): z selects Q/K/V; epilogue applies RoPE + writes fp16 buffers
// directly (Qh / Kch scatter / Vh), skipping the fp32 intermediates.
#define HG_STAGE 20480
#define HG_SMEM  81920

template <typename OutT, bool CAUSAL, bool TRUNC, bool FUSE>
__global__ __launch_bounds__(256, 2) void hgemm(
    const __half* __restrict__ A, const __half* __restrict__ B, OutT* __restrict__ C,
    int K, int lda, int ldb, int ldc,
    long long aSb, long long aSh, long long bSb, long long bSh,
    long long cSb, long long cSh, int nh,
    const float* __restrict__ fc, const float* __restrict__ fs)
{
    const int m0 = blockIdx.y * 128, n0 = blockIdx.x * 128;
    if (CAUSAL && n0 > m0 + 127 + ALEN) return;   // fully-masked score tile

    extern __shared__ char smem[];
    const uint32_t sb = smem_to_u32(smem);
    int zb = blockIdx.z / nh, zh = blockIdx.z % nh;
    A += zb*aSb + zh*aSh;
    B += zb*bSb + zh*bSh;
    C += zb*cSb + zh*cSh;

    const int tid = threadIdx.x, lane = tid & 31, warp = tid >> 5;
    const int wm = warp & 1, wn = warp >> 1;       // warp tile 64(m) x 32(n)

    const int Keff = TRUNC ? min(K, (m0 + 128 + ALEN + 31) & ~31) : K;
    const int nch = Keff >> 5;                     // >= 4 for all our shapes

    // copy mapping: thread -> row tid>>1, two 16B segs at (tid&1)*32 bytes
    const int crow = tid >> 1;
    const int cseg = (tid & 1) * 2;
    const __half* ag = A + (long long)(m0 + crow) * lda + cseg * 8;
    const __half* bg = B + (long long)(n0 + crow) * ldb + cseg * 8;
    const uint32_t sa = sb + crow*80 + cseg*16;
    const uint32_t sbb = sb + 10240 + crow*80 + cseg*16;

    float acc[4][4][4];
    #pragma unroll
    for (int mi = 0; mi < 4; mi++)
        #pragma unroll
        for (int ni = 0; ni < 4; ni++)
            #pragma unroll
            for (int j = 0; j < 4; j++) acc[mi][ni][j] = 0.f;

    // prologue: stages 0..2
    #pragma unroll
    for (int s = 0; s < 3; s++) {
        CP16(sa  + s*HG_STAGE,      ag + s*32);
        CP16(sa  + s*HG_STAGE + 16, ag + s*32 + 8);
        CP16(sbb + s*HG_STAGE,      bg + s*32);
        CP16(sbb + s*HG_STAGE + 16, bg + s*32 + 8);
        CP_COMMIT();
    }

    const int rsel = lane & 15, csel = lane >> 4;

    for (int c = 0; c < nch; c++) {
        CP_WAIT2();
        __syncthreads();

        const uint32_t abase = sb + (c & 3)*HG_STAGE + (wm*64)*80;
        const uint32_t bbase = sb + (c & 3)*HG_STAGE + 10240 + (wn*32)*80;

        uint32_t a[4][4], b[2][2][4];
        #pragma unroll
        for (int nj = 0; nj < 2; nj++)
            LDSM4(b[0][nj], bbase + (nj*16 + rsel)*80 + csel*16);
        #pragma unroll
        for (int nj = 0; nj < 2; nj++)
            LDSM4(b[1][nj], bbase + (nj*16 + rsel)*80 + 32 + csel*16);
        #pragma unroll
        for (int mi = 0; mi < 4; mi++)
            LDSM4(a[mi], abase + (mi*16 + rsel)*80 + csel*16);

        int nxt = c + 3;
        if (nxt < nch) {
            int s = nxt & 3;
            CP16(sa  + s*HG_STAGE,      ag + nxt*32);
            CP16(sa  + s*HG_STAGE + 16, ag + nxt*32 + 8);
            CP16(sbb + s*HG_STAGE,      bg + nxt*32);
            CP16(sbb + s*HG_STAGE + 16, bg + nxt*32 + 8);
        }
        CP_COMMIT();

        // ks = 0, each mi's MMAs followed by that mi's ks1 A reload
        #pragma unroll
        for (int mi = 0; mi < 4; mi++) {
            #pragma unroll
            for (int ni = 0; ni < 4; ni++)
                mma16(acc[mi][ni], a[mi], b[0][ni>>1][ni&1], b[0][ni>>1][(ni&1)+2]);
            LDSM4(a[mi], abase + (mi*16 + rsel)*80 + 32 + csel*16);
        }
        // ks = 1
        #pragma unroll
        for (int mi = 0; mi < 4; mi++)
            #pragma unroll
            for (int ni = 0; ni < 4; ni++)
                mma16(acc[mi][ni], a[mi], b[1][ni>>1][ni&1], b[1][ni>>1][(ni&1)+2]);
    }

    const int er = lane >> 2, ec = (lane & 3) * 2;

    if (FUSE) {
        // zh: 0=Q(rope->Qh), 1=K(rope+scatter->Kch), 2=V(->Vh fp16)
        #pragma unroll
        for (int mi = 0; mi < 4; mi++) {
            #pragma unroll
            for (int ni = 0; ni < 4; ni++) {
                int row = m0 + wm*64 + mi*16 + er;
                int col = n0 + wn*32 + ni*8 + ec;
                float* cc = acc[mi][ni];
                int d = col & (HDIM-1), h = col >> 7, p = d >> 1;
                #pragma unroll
                for (int rr = 0; rr < 2; rr++) {
                    int r_ = row + rr*8;
                    float vx = cc[rr*2], vy = cc[rr*2 + 1];
                    if (zh == 2) {
                        *(__half2*)(g_Vh + (long long)r_*DIMM + col) = __floats2half2_rn(vx, vy);
                    } else if (r_ < BS*SEQL) {
                        int q = r_ & (SEQL-1);
                        float cv = fc[q*64 + p], sv = fs[q*64 + p];
                        __half2 o = __floats2half2_rn(vx*cv - vy*sv, vx*sv + vy*cv);
                        if (zh == 0) {
                            *(__half2*)(g_Qh + (long long)r_*DIMM + col) = o;
                        } else {
                            int b = r_ >> 10;
                            *(__half2*)(g_Kch +
                                ((long long)(b*NHEADS + h)*KCAT + ALEN + q)*HDIM + d) = o;
                        }
                    } else if (zh == 1 && r_ < BS*SEQL + ALEN) {
                        int j = r_ - BS*SEQL;          // adapter row, un-roped, both batches
                        __half2 o = __floats2half2_rn(vx, vy);
                        *(__half2*)(g_Kch + ((long long)h*KCAT + j)*HDIM + d) = o;
                        *(__half2*)(g_Kch + ((long long)(NHEADS + h)*KCAT + j)*HDIM + d) = o;
                    }
                }
            }
        }
        return;
    }

    #pragma unroll
    for (int mi = 0; mi < 4; mi++) {
        #pragma unroll
        for (int ni = 0; ni < 4; ni++) {
            int row = m0 + wm*64 + mi*16 + er;
            int col = n0 + wn*32 + ni*8 + ec;
            float* cc = acc[mi][ni];
            if (sizeof(OutT) == 4) {
                *(float2*)((float*)C + (long long)row * ldc + col) = make_float2(cc[0], cc[1]);
                *(float2*)((float*)C + (long long)(row+8) * ldc + col) = make_float2(cc[2], cc[3]);
            } else {
                *(__half2*)((__half*)C + (long long)row * ldc + col) = __floats2half2_rn(cc[0], cc[1]);
                *(__half2*)((__half*)C + (long long)(row+8) * ldc + col) = __floats2half2_rn(cc[2], cc[3]);
            }
        }
    }
}

// ---------------- fp32 -> fp16 conversion, 4 float4 per thread (MLP=4) ------
__global__ void f2h_kernel(const float* __restrict__ in, __half* __restrict__ out) {
    int base = blockIdx.x * 1024 + threadIdx.x;
    float4 v[4];
    #pragma unroll
    for (int j = 0; j < 4; j++) v[j] = ((const float4*)in)[base + j*256];
    #pragma unroll
    for (int j = 0; j < 4; j++) {
        int i = base + j*256;
        ((__half2*)out)[2*i]   = __floats2half2_rn(v[j].x, v[j].y);
        ((__half2*)out)[2*i+1] = __floats2half2_rn(v[j].z, v[j].w);
    }
}

// all 4 weight matrices in one launch; wq/wk/wv into contiguous g_wh
__global__ void f2h4_kernel(const float* __restrict__ w0, const float* __restrict__ w1,
                            const float* __restrict__ w2, const float* __restrict__ w3,
                            __half* __restrict__ wh, __half* __restrict__ woh) {
    const float* in;  __half* out;
    switch (blockIdx.y) {
        case 0: in = w0; out = wh; break;
        case 1: in = w1; out = wh + (long long)DIMM*DIMM; break;
        case 2: in = w2; out = wh + 2LL*DIMM*DIMM; break;
        default: in = w3; out = woh; break;
    }
    int base = blockIdx.x * 1024 + threadIdx.x;
    float4 v[4];
    #pragma unroll
    for (int j = 0; j < 4; j++) v[j] = ((const float4*)in)[base + j*256];
    #pragma unroll
    for (int j = 0; j < 4; j++) {
        int i = base + j*256;
        ((__half2*)out)[2*i]   = __floats2half2_rn(v[j].x, v[j].y);
        ((__half2*)out)[2*i+1] = __floats2half2_rn(v[j].z, v[j].w);
    }
}

// ---------------- adapter rows -> xh rows 2048..2175 (10 real + zero pad) ---
__global__ void adapter_fill_kernel(const float* __restrict__ adp) {
    int i = blockIdx.x * 256 + threadIdx.x;     // over 128*2048/8 = 32768 uint4
    int row = i >> 8;                           // 256 8-half chunks per row
    int c8 = (i & 255) * 8;
    __half h[8];
    if (row < ALEN) {
        #pragma unroll
        for (int j = 0; j < 8; j++) h[j] = __float2half(adp[row*DIMM + c8 + j]);
    } else {
        #pragma unroll
        for (int j = 0; j < 8; j++) h[j] = __float2half(0.f);
    }
    *(uint4*)(g_xh + (long long)(BS*SEQL + row)*DIMM + c8) = *(uint4*)h;
}

// ---------------- zero the Kch pad rows [ALEN+SEQL, KCAT) for all z ---------
__global__ void zero_pad_kc_kernel() {
    int i = blockIdx.x * 256 + threadIdx.x;     // 32*118*64 = 241664 half2
    int d2 = i & 63;
    int rz = i >> 6;
    int r = (ALEN + SEQL) + rz % (KCAT - ALEN - SEQL);
    int z = rz / (KCAT - ALEN - SEQL);
    *(__half2*)(g_Kch + ((long long)z*KCAT + r)*HDIM + 2*d2) = __floats2half2_rn(0.f, 0.f);
}

// ---------------- transposed [adapter|values|pad] V (fp16 in) ---------------
__global__ void transpose_v_kernel()
{
    __shared__ float tile[32][33];
    int z = blockIdx.z;
    int b = z >> 4, h = z & 15;
    int kt = blockIdx.x * 32, dt = blockIdx.y * 32;
    int tx = threadIdx.x, ty = threadIdx.y;   // 32 x 8
    #pragma unroll
    for (int j = 0; j < 4; j++) {
        int k = kt + ty + 8*j;
        int d = dt + tx;
        float v = 0.f;
        if (k < ALEN) v = __half2float(g_Vh[(long long)(BS*SEQL + k)*DIMM + h*HDIM + d]);
        else if (k < ALEN + SEQL)
            v = __half2float(g_Vh[((long long)(b * SEQL + k - ALEN)) * DIMM + h * HDIM + d]);
        tile[ty + 8*j][tx] = v;
    }
    __syncthreads();
    #pragma unroll
    for (int j = 0; j < 4; j++) {
        int d = dt + ty + 8*j;
        g_Vth[((long long)z * HDIM + d) * KCAT + kt + tx] = __float2half(tile[tx][ty + 8*j]);
    }
}

// ---------------- softmax: warp per row, shfl-only reductions ---------------
__global__ __launch_bounds__(256) void softmax_kernel(
    const float* __restrict__ S,
    const float* __restrict__ gate1,
    const float* __restrict__ gate2,
    const int*   __restrict__ vsp)
{
    const int rowid = blockIdx.x * 8 + (threadIdx.x >> 5);   // BS*NHEADS*SEQL rows
    const int lane = threadIdx.x & 31;
    const int z = rowid >> 10, q = rowid & 1023, h = z & 15;
    const float* row = S + (long long)rowid * KCAT;
    __half* hrow = g_Ph + (long long)rowid * KCAT;
    const int vs = *vsp;
    const float scale = 0.08838834764831843f;   // 1/sqrt(128)
    const float g2 = gate2[h];
    const bool grow = (q >= vs + MAXF);

    float e[32];
    float lmax = -1e30f;
    #pragma unroll
    for (int i = 0; i < 32; i++) {
        int k = i*32 + lane;
        float v = -1e30f;
        if (k <= q) {
            v = row[ALEN + k] * scale;
            if (grow && k >= vs && k < vs + MAXF) v += g2;
        }
        e[i] = v;  lmax = fmaxf(lmax, v);
    }
    #pragma unroll
    for (int o = 16; o > 0; o >>= 1) lmax = fmaxf(lmax, __shfl_xor_sync(0xffffffffu, lmax, o));

    float lsum = 0.f;
    #pragma unroll
    for (int i = 0; i < 32; i++) {
        int k = i*32 + lane;
        float x = (k <= q) ? expf(e[i] - lmax) : 0.f;
        e[i] = x;  lsum += x;
    }
    #pragma unroll
    for (int o = 16; o > 0; o >>= 1) lsum += __shfl_xor_sync(0xffffffffu, lsum, o);
    float inv = 1.0f / lsum;

    #pragma unroll
    for (int i = 0; i < 32; i++)
        hrow[ALEN + i*32 + lane] = __float2half(e[i] * inv);
    for (int k = SEQL + lane; k < KCAT - ALEN; k += 32)     // zero pad cols
        hrow[ALEN + k] = __float2half(0.f);

    // adapter segment: separate softmax * tanh(gate1[h])
    float av = (lane < ALEN) ? row[lane] * scale : -1e30f;
    float am = av;
    #pragma unroll
    for (int o = 16; o > 0; o >>= 1) am = fmaxf(am, __shfl_xor_sync(0xffffffffu, am, o));
    float ae = (lane < ALEN) ? expf(av - am) : 0.f;
    float as = ae;
    #pragma unroll
    for (int o = 16; o > 0; o >>= 1) as += __shfl_xor_sync(0xffffffffu, as, o);
    if (lane < ALEN) hrow[lane] = __float2half(ae * tanhf(gate1[h]) / as);
}

// ---------------- launch -----------------------------------------------------
extern "C" void kernel_launch(void* const* d_in, const int* in_sizes, int n_in,
                              void* d_out, int out_size)
{
    const float* x   = (const float*)d_in[0];
    const float* adp = (const float*)d_in[1];
    /* d_in[2] = mask: equivalent to hard causal mask, recomputed on device */
    const float* fc  = (const float*)d_in[3];
    const float* fs  = (const float*)d_in[4];
    const float* wq  = (const float*)d_in[5];
    const float* wk  = (const float*)d_in[6];
    const float* wv  = (const float*)d_in[7];
    const float* wo  = (const float*)d_in[8];
    const float* g1  = (const float*)d_in[9];
    const float* g2  = (const float*)d_in[10];
    const int*   vsp = (const int*)d_in[11];
    float* out = (float*)d_out;

    float *Sp;
    __half *xh, *wh, *woh, *Qhp, *Kchp, *Vthp, *Php, *Ohp;
    cudaGetSymbolAddress((void**)&Sp,  g_S);
    cudaGetSymbolAddress((void**)&xh,  g_xh);
    cudaGetSymbolAddress((void**)&wh,  g_wh);
    cudaGetSymbolAddress((void**)&woh, g_woh);
    cudaGetSymbolAddress((void**)&Qhp, g_Qh);
    cudaGetSymbolAddress((void**)&Kchp, g_Kch);
    cudaGetSymbolAddress((void**)&Vthp, g_Vth);
    cudaGetSymbolAddress((void**)&Php, g_Ph);
    cudaGetSymbolAddress((void**)&Ohp, g_Oh);

    cudaFuncSetAttribute((const void*)hgemm<float,false,false,true>,  cudaFuncAttributeMaxDynamicSharedMemorySize, HG_SMEM);
    cudaFuncSetAttribute((const void*)hgemm<float,false,false,false>, cudaFuncAttributeMaxDynamicSharedMemorySize, HG_SMEM);
    cudaFuncSetAttribute((const void*)hgemm<float,true,false,false>,  cudaFuncAttributeMaxDynamicSharedMemorySize, HG_SMEM);
    cudaFuncSetAttribute((const void*)hgemm<__half,false,true,false>, cudaFuncAttributeMaxDynamicSharedMemorySize, HG_SMEM);

    // fp32 -> fp16 conversions + adapter rows into xh + Kch pad-zero
    f2h_kernel<<<BS*SEQL*DIMM/4096, 256>>>(x, xh);
    f2h4_kernel<<<dim3(DIMM*DIMM/4096, 4), 256>>>(wq, wk, wv, wo, wh, woh);
    adapter_fill_kernel<<<128, 256>>>(adp);
    zero_pad_kc_kernel<<<944, 256>>>();

    // QKV projections fused (M=2176 incl. adapter rows) with rope/scatter epilogue
    hgemm<float,false,false,true><<<dim3(DIMM/128, MPAD/128, 3), 256, HG_SMEM>>>(
        xh, wh, Sp /*unused*/, DIMM, DIMM, DIMM, DIMM,
        0, 0, 0, (long long)DIMM*DIMM,
        0, 0, 3, fc, fs);

    transpose_v_kernel<<<dim3(KCAT/32, HDIM/32, BS*NHEADS), dim3(32, 8)>>>();

    // scores: per z: S(1024x1152) = Qh(1024x128) @ Kch^T  (causal tile skip)
    hgemm<float,true,false,false><<<dim3(KCAT/128, SEQL/128, BS*NHEADS), 256, HG_SMEM>>>(
        Qhp, Kchp, Sp, HDIM,
        DIMM, HDIM, KCAT,
        (long long)SEQL*DIMM, (long long)HDIM,
        (long long)NHEADS*KCAT*HDIM, (long long)KCAT*HDIM,
        (long long)NHEADS*SEQL*KCAT, (long long)SEQL*KCAT, NHEADS, nullptr, nullptr);

    softmax_kernel<<<BS*NHEADS*SEQL/8, 256>>>(Sp, g1, g2, vsp);

    // attn: per z: Oh(1024x128) = Ph(1024x1152) @ Vth(128x1152)^T  (K-truncated)
    hgemm<__half,false,true,false><<<dim3(1, SEQL/128, BS*NHEADS), 256, HG_SMEM>>>(
        Php, Vthp, Ohp, KCAT,
        KCAT, KCAT, DIMM,
        (long long)NHEADS*SEQL*KCAT, (long long)SEQL*KCAT,
        (long long)NHEADS*HDIM*KCAT, (long long)HDIM*KCAT,
        (long long)SEQL*DIMM, (long long)HDIM, NHEADS, nullptr, nullptr);

    // output projection: fp32 out to d_out
    hgemm<float,false,false,false><<<dim3(DIMM/128, (BS*SEQL)/128, 1), 256, HG_SMEM>>>(
        Ohp, woh, out, DIMM, DIMM, DIMM, DIMM, 0,0,0,0,0,0, 1, nullptr, nullptr);
}

// round 14
// speedup vs baseline: 1.5338x; 1.3072x over previous
#include <cuda_runtime.h>
#include <cuda_fp16.h>
#include <math.h>
#include <stdint.h>

#define DIMM   2048
#define NHEADS 16
#define HDIM   128
#define SEQL   1024
#define BS     2
#define ALEN   10
#define MAXF   10
#define KCAT   1152   /* 10 adapter + 1024 keys + 118 zero pad = 9*128 */
#define MPAD   (BS*SEQL + 128)   /* 2176: x rows + adapter row tile */
#define QSCALE 0.08838834764831843f

// ---------------- scratch (device globals; no allocation allowed) ----------
__device__ __half g_xh [MPAD*DIMM];          // x (2048) | adapter (10) | zeros
__device__ __half g_wh [3*DIMM*DIMM];        // wq|wk|wv fp16 contiguous
__device__ __half g_woh[DIMM*DIMM];
__device__ __half g_Qh [BS*SEQL*DIMM];       // roped + pre-scaled Q
__device__ __half g_Vh [MPAD*DIMM];          // V fp16 (incl. adapter rows)
__device__ __half g_Kch[BS*NHEADS*KCAT*HDIM];
__device__ __half g_Vth[BS*NHEADS*HDIM*KCAT];   // V transposed: [z][d][k]
__device__ __half g_Oh [BS*SEQL*DIMM];

// ---------------- PTX helpers ----------------------------------------------
__device__ __forceinline__ uint32_t smem_to_u32(const void* p) {
    uint32_t a;
    asm("{ .reg .u64 t; cvta.to.shared.u64 t, %1; cvt.u32.u64 %0, t; }" : "=r"(a) : "l"(p));
    return a;
}
#define CP16(dst, src) \
    asm volatile("cp.async.cg.shared.global [%0], [%1], 16;" :: "r"(dst), "l"(src))
#define CP_COMMIT() asm volatile("cp.async.commit_group;" ::: "memory")
#define CP_WAIT0()  asm volatile("cp.async.wait_group 0;" ::: "memory")
#define CP_WAIT1()  asm volatile("cp.async.wait_group 1;" ::: "memory")
#define CP_WAIT2()  asm volatile("cp.async.wait_group 2;" ::: "memory")

#define LDSM4(r, a) \
    asm volatile("ldmatrix.sync.aligned.m8n8.x4.shared.b16 {%0,%1,%2,%3},[%4];" \
        : "=r"((r)[0]), "=r"((r)[1]), "=r"((r)[2]), "=r"((r)[3]) : "r"(a))

__device__ __forceinline__ void mma16(float* c, const uint32_t* a, uint32_t b0, uint32_t b1) {
    asm volatile(
        "mma.sync.aligned.m16n8k16.row.col.f32.f16.f16.f32 "
        "{%0,%1,%2,%3},{%4,%5,%6,%7},{%8,%9},{%0,%1,%2,%3};"
        : "+f"(c[0]), "+f"(c[1]), "+f"(c[2]), "+f"(c[3])
        : "r"(a[0]), "r"(a[1]), "r"(a[2]), "r"(a[3]), "r"(b0), "r"(b1));
}

// ---------------- fp16 tensor-core batched GEMM: C = A @ B^T ----------------
// CTA tile 128x128, 8 warps (2m x 4n), warp tile 64x32, BK=32, 4-stage cp.async.
#define HG_STAGE 20480
#define HG_SMEM  81920

template <typename OutT, bool FUSE>
__global__ __launch_bounds__(256, 2) void hgemm(
    const __half* __restrict__ A, const __half* __restrict__ B, OutT* __restrict__ C,
    int K, int lda, int ldb, int ldc,
    long long bSh, long long cSh, int nh,
    const float* __restrict__ fc, const float* __restrict__ fs)
{
    const int m0 = blockIdx.y * 128, n0 = blockIdx.x * 128;
    extern __shared__ char smem[];
    const uint32_t sb = smem_to_u32(smem);
    int zh = blockIdx.z % nh;
    B += zh*bSh;
    C += zh*cSh;

    const int tid = threadIdx.x, lane = tid & 31, warp = tid >> 5;
    const int wm = warp & 1, wn = warp >> 1;       // warp tile 64(m) x 32(n)
    const int nch = K >> 5;

    const int crow = tid >> 1;
    const int cseg = (tid & 1) * 2;
    const __half* ag = A + (long long)(m0 + crow) * lda + cseg * 8;
    const __half* bg = B + (long long)(n0 + crow) * ldb + cseg * 8;
    const uint32_t sa = sb + crow*80 + cseg*16;
    const uint32_t sbb = sb + 10240 + crow*80 + cseg*16;

    float acc[4][4][4];
    #pragma unroll
    for (int mi = 0; mi < 4; mi++)
        #pragma unroll
        for (int ni = 0; ni < 4; ni++)
            #pragma unroll
            for (int j = 0; j < 4; j++) acc[mi][ni][j] = 0.f;

    #pragma unroll
    for (int s = 0; s < 3; s++) {
        CP16(sa  + s*HG_STAGE,      ag + s*32);
        CP16(sa  + s*HG_STAGE + 16, ag + s*32 + 8);
        CP16(sbb + s*HG_STAGE,      bg + s*32);
        CP16(sbb + s*HG_STAGE + 16, bg + s*32 + 8);
        CP_COMMIT();
    }

    const int rsel = lane & 15, csel = lane >> 4;

    for (int c = 0; c < nch; c++) {
        CP_WAIT2();
        __syncthreads();

        const uint32_t abase = sb + (c & 3)*HG_STAGE + (wm*64)*80;
        const uint32_t bbase = sb + (c & 3)*HG_STAGE + 10240 + (wn*32)*80;

        uint32_t a[4][4], b[2][2][4];
        #pragma unroll
        for (int nj = 0; nj < 2; nj++)
            LDSM4(b[0][nj], bbase + (nj*16 + rsel)*80 + csel*16);
        #pragma unroll
        for (int nj = 0; nj < 2; nj++)
            LDSM4(b[1][nj], bbase + (nj*16 + rsel)*80 + 32 + csel*16);
        #pragma unroll
        for (int mi = 0; mi < 4; mi++)
            LDSM4(a[mi], abase + (mi*16 + rsel)*80 + csel*16);

        int nxt = c + 3;
        if (nxt < nch) {
            int s = nxt & 3;
            CP16(sa  + s*HG_STAGE,      ag + nxt*32);
            CP16(sa  + s*HG_STAGE + 16, ag + nxt*32 + 8);
            CP16(sbb + s*HG_STAGE,      bg + nxt*32);
            CP16(sbb + s*HG_STAGE + 16, bg + nxt*32 + 8);
        }
        CP_COMMIT();

        #pragma unroll
        for (int mi = 0; mi < 4; mi++) {
            #pragma unroll
            for (int ni = 0; ni < 4; ni++)
                mma16(acc[mi][ni], a[mi], b[0][ni>>1][ni&1], b[0][ni>>1][(ni&1)+2]);
            LDSM4(a[mi], abase + (mi*16 + rsel)*80 + 32 + csel*16);
        }
        #pragma unroll
        for (int mi = 0; mi < 4; mi++)
            #pragma unroll
            for (int ni = 0; ni < 4; ni++)
                mma16(acc[mi][ni], a[mi], b[1][ni>>1][ni&1], b[1][ni>>1][(ni&1)+2]);
    }

    const int er = lane >> 2, ec = (lane & 3) * 2;

    if (FUSE) {
        // zh: 0=Q(rope+scale->Qh), 1=K(rope+scatter->Kch), 2=V(->Vh fp16)
        #pragma unroll
        for (int mi = 0; mi < 4; mi++) {
            #pragma unroll
            for (int ni = 0; ni < 4; ni++) {
                int row = m0 + wm*64 + mi*16 + er;
                int col = n0 + wn*32 + ni*8 + ec;
                float* cc = acc[mi][ni];
                int d = col & (HDIM-1), h = col >> 7, p = d >> 1;
                #pragma unroll
                for (int rr = 0; rr < 2; rr++) {
                    int r_ = row + rr*8;
                    float vx = cc[rr*2], vy = cc[rr*2 + 1];
                    if (zh == 2) {
                        *(__half2*)(g_Vh + (long long)r_*DIMM + col) = __floats2half2_rn(vx, vy);
                    } else if (r_ < BS*SEQL) {
                        int q = r_ & (SEQL-1);
                        float cv = fc[q*64 + p], sv = fs[q*64 + p];
                        float ox = vx*cv - vy*sv, oy = vx*sv + vy*cv;
                        if (zh == 0) {
                            *(__half2*)(g_Qh + (long long)r_*DIMM + col) =
                                __floats2half2_rn(ox*QSCALE, oy*QSCALE);
                        } else {
                            int b = r_ >> 10;
                            *(__half2*)(g_Kch +
                                ((long long)(b*NHEADS + h)*KCAT + ALEN + q)*HDIM + d) =
                                __floats2half2_rn(ox, oy);
                        }
                    } else if (zh == 1 && r_ < BS*SEQL + ALEN) {
                        int j = r_ - BS*SEQL;
                        __half2 o = __floats2half2_rn(vx, vy);
                        *(__half2*)(g_Kch + ((long long)h*KCAT + j)*HDIM + d) = o;
                        *(__half2*)(g_Kch + ((long long)(NHEADS + h)*KCAT + j)*HDIM + d) = o;
                    }
                }
            }
        }
        return;
    }

    #pragma unroll
    for (int mi = 0; mi < 4; mi++) {
        #pragma unroll
        for (int ni = 0; ni < 4; ni++) {
            int row = m0 + wm*64 + mi*16 + er;
            int col = n0 + wn*32 + ni*8 + ec;
            float* cc = acc[mi][ni];
            *(float2*)((float*)C + (long long)row * ldc + col) = make_float2(cc[0], cc[1]);
            *(float2*)((float*)C + (long long)(row+8) * ldc + col) = make_float2(cc[2], cc[3]);
        }
    }
}

// ---------------- fused flash attention -------------------------------------
// CTA: 128 thr (4 warps), 64 q-rows, one (b,h). Loop over 128-wide k-tiles of
// Kch/Vth with online softmax; adapter segment handled via separate softmax +
// one extra k16 MMA at the end. Warp owns 16 rows x full 128 cols.
#define FA_PITCH  272                     /* 256B data + 16B pad */
#define FA_K_OFF  17408                   /* 64*272 Q tile */
#define FA_V_OFF  (17408 + 34816)
#define FA_VA_OFF (FA_V_OFF + 34816)      /* 128 x 48B adapter-V block */
#define FA_SMEM   (FA_VA_OFF + 6144)      /* 93184 */

__global__ __launch_bounds__(128, 2) void flash_kernel(
    const float* __restrict__ gate1, const float* __restrict__ gate2,
    const int* __restrict__ vsp)
{
    extern __shared__ char smem[];
    const uint32_t sb = smem_to_u32(smem);
    const int bx = blockIdx.x;
    const int z = bx & 31;
    const int mi = 15 - (bx >> 5);        // heavy tiles first (LPT)
    const int m0 = mi * 64;
    const int b = z >> 4, h = z & 15;
    const int tid = threadIdx.x, lane = tid & 31, warp = tid >> 5;
    const int rsel = lane & 15, csel = lane >> 4;
    const int er = lane >> 2, ec = (lane & 3) * 2;
    const int vs = *vsp;
    const float g2 = gate2[h];

    const __half* Qg = g_Qh + ((long long)(b*SEQL + m0))*DIMM + h*HDIM;
    const __half* Kg = g_Kch + (long long)z*KCAT*HDIM;
    const __half* Vg = g_Vth + (long long)z*HDIM*KCAT;

    // prologue: Q tile, adapter-V block, K0, V0 (one commit group)
    {
        int row = tid >> 1, seg = tid & 1;
        const __half* src = Qg + (long long)row*DIMM + seg*64;
        uint32_t dst = sb + row*FA_PITCH + seg*128;
        #pragma unroll
        for (int i = 0; i < 8; i++) CP16(dst + i*16, src + i*8);
    }
    {
        const __half* src = Vg + (long long)tid*KCAT;
        uint32_t dst = sb + FA_VA_OFF + tid*48;
        CP16(dst, src); CP16(dst + 16, src + 8);
    }
    {
        const __half* ks = Kg + tid*HDIM;
        uint32_t kd = sb + FA_K_OFF + tid*FA_PITCH;
        #pragma unroll
        for (int i = 0; i < 16; i++) CP16(kd + i*16, ks + i*8);
        const __half* vsrc = Vg + (long long)tid*KCAT;
        uint32_t vd = sb + FA_V_OFF + tid*FA_PITCH;
        #pragma unroll
        for (int i = 0; i < 16; i++) CP16(vd + i*16, vsrc + i*8);
    }
    CP_COMMIT();

    const int q0 = m0 + warp*16 + er, q1 = q0 + 8;
    const bool grow0 = q0 >= vs + MAXF, grow1 = q1 >= vs + MAXF;

    float oacc[16][4];
    #pragma unroll
    for (int n = 0; n < 16; n++)
        oacc[n][0] = oacc[n][1] = oacc[n][2] = oacc[n][3] = 0.f;
    float m0r = -1e30f, m1r = -1e30f, l0 = 0.f, l1 = 0.f;
    float ad[4], adx[4];

    const int nkt = (m0 + 73)/128 + 1;

    for (int kt = 0; kt < nkt; kt++) {
        if (kt == 0) CP_WAIT0(); else CP_WAIT1();
        __syncthreads();

        float sacc[16][4];
        #pragma unroll
        for (int n = 0; n < 16; n++)
            sacc[n][0] = sacc[n][1] = sacc[n][2] = sacc[n][3] = 0.f;

        // S = Q @ K_tile^T
        #pragma unroll
        for (int kk = 0; kk < 8; kk++) {
            uint32_t a[4], bf[8][4];
            LDSM4(a, sb + (warp*16 + rsel)*FA_PITCH + kk*32 + csel*16);
            #pragma unroll
            for (int nj = 0; nj < 8; nj++)
                LDSM4(bf[nj], sb + FA_K_OFF + (nj*16 + rsel)*FA_PITCH + kk*32 + csel*16);
            #pragma unroll
            for (int ni = 0; ni < 16; ni++)
                mma16(sacc[ni], a, bf[ni>>1][ni&1], bf[ni>>1][(ni&1)+2]);
        }
        __syncthreads();                       // done reading K smem
        if (kt + 1 < nkt) {                    // prefetch K[kt+1]
            const __half* src = Kg + (long long)(kt+1)*128*HDIM + tid*HDIM;
            uint32_t dst = sb + FA_K_OFF + tid*FA_PITCH;
            #pragma unroll
            for (int i = 0; i < 16; i++) CP16(dst + i*16, src + i*8);
        }
        CP_COMMIT();

        if (kt == 0) {                         // raw adapter logits (cols 0..9)
            #pragma unroll
            for (int j = 0; j < 4; j++) { ad[j] = sacc[0][j]; adx[j] = sacc[1][j]; }
        }

        // mask + gate2 + row max
        float mx0 = -1e30f, mx1 = -1e30f;
        #pragma unroll
        for (int ni = 0; ni < 16; ni++) {
            #pragma unroll
            for (int j = 0; j < 4; j++) {
                int kkey = kt*128 + ni*8 + ec + (j & 1) - ALEN;
                int q = (j < 2) ? q0 : q1;
                bool gr = (j < 2) ? grow0 : grow1;
                float s = sacc[ni][j];
                bool val = (kkey >= 0) && (kkey <= q);
                if (val && gr && kkey >= vs && kkey < vs + MAXF) s += g2;
                s = val ? s : -1e30f;
                sacc[ni][j] = s;
                if (j < 2) mx0 = fmaxf(mx0, s); else mx1 = fmaxf(mx1, s);
            }
        }
        mx0 = fmaxf(mx0, __shfl_xor_sync(0xffffffffu, mx0, 1));
        mx0 = fmaxf(mx0, __shfl_xor_sync(0xffffffffu, mx0, 2));
        mx1 = fmaxf(mx1, __shfl_xor_sync(0xffffffffu, mx1, 1));
        mx1 = fmaxf(mx1, __shfl_xor_sync(0xffffffffu, mx1, 2));
        float nm0 = fmaxf(m0r, mx0), nm1 = fmaxf(m1r, mx1);
        float sc0 = __expf(m0r - nm0), sc1 = __expf(m1r - nm1);
        m0r = nm0; m1r = nm1;
        l0 *= sc0; l1 *= sc1;
        #pragma unroll
        for (int n = 0; n < 16; n++) {
            oacc[n][0] *= sc0; oacc[n][1] *= sc0;
            oacc[n][2] *= sc1; oacc[n][3] *= sc1;
        }

        uint32_t pu[16][2];
        float s0 = 0.f, s1 = 0.f;
        #pragma unroll
        for (int ni = 0; ni < 16; ni++) {
            float p0 = __expf(sacc[ni][0] - m0r);
            float p1 = __expf(sacc[ni][1] - m0r);
            float p2 = __expf(sacc[ni][2] - m1r);
            float p3 = __expf(sacc[ni][3] - m1r);
            s0 += p0 + p1; s1 += p2 + p3;
            __half2 h0 = __floats2half2_rn(p0, p1);
            __half2 h1 = __floats2half2_rn(p2, p3);
            pu[ni][0] = *(uint32_t*)&h0;
            pu[ni][1] = *(uint32_t*)&h1;
        }
        s0 += __shfl_xor_sync(0xffffffffu, s0, 1);
        s0 += __shfl_xor_sync(0xffffffffu, s0, 2);
        s1 += __shfl_xor_sync(0xffffffffu, s1, 1);
        s1 += __shfl_xor_sync(0xffffffffu, s1, 2);
        l0 += s0; l1 += s1;

        CP_WAIT1();                            // V[kt] ready
        __syncthreads();

        // O += P @ V_tile^T  (P from registers)
        #pragma unroll
        for (int kk = 0; kk < 8; kk++) {
            uint32_t vb[8][4];
            #pragma unroll
            for (int nj = 0; nj < 8; nj++)
                LDSM4(vb[nj], sb + FA_V_OFF + (nj*16 + rsel)*FA_PITCH + kk*32 + csel*16);
            uint32_t ap[4] = { pu[2*kk][0], pu[2*kk][1], pu[2*kk+1][0], pu[2*kk+1][1] };
            #pragma unroll
            for (int ni = 0; ni < 16; ni++)
                mma16(oacc[ni], ap, vb[ni>>1][ni&1], vb[ni>>1][(ni&1)+2]);
        }
        __syncthreads();                       // done reading V smem
        if (kt + 1 < nkt) {                    // prefetch V[kt+1]
            const __half* src = Vg + (long long)tid*KCAT + (kt+1)*128;
            uint32_t dst = sb + FA_V_OFF + tid*FA_PITCH;
            #pragma unroll
            for (int i = 0; i < 16; i++) CP16(dst + i*16, src + i*8);
        }
        CP_COMMIT();
    }

    // normalize main part
    float inv0 = 1.f / l0, inv1 = 1.f / l1;
    #pragma unroll
    for (int n = 0; n < 16; n++) {
        oacc[n][0] *= inv0; oacc[n][1] *= inv0;
        oacc[n][2] *= inv1; oacc[n][3] *= inv1;
    }

    // adapter segment: separate softmax * tanh(gate1[h]) + one k16 MMA
    {
        float g1t = tanhf(gate1[h]);
        bool hasx = (ec == 0);                 // cols 8,9 live on quad lane 0
        float am0 = fmaxf(ad[0], ad[1]);
        float am1 = fmaxf(ad[2], ad[3]);
        if (hasx) { am0 = fmaxf(am0, fmaxf(adx[0], adx[1]));
                    am1 = fmaxf(am1, fmaxf(adx[2], adx[3])); }
        am0 = fmaxf(am0, __shfl_xor_sync(0xffffffffu, am0, 1));
        am0 = fmaxf(am0, __shfl_xor_sync(0xffffffffu, am0, 2));
        am1 = fmaxf(am1, __shfl_xor_sync(0xffffffffu, am1, 1));
        am1 = fmaxf(am1, __shfl_xor_sync(0xffffffffu, am1, 2));
        float e0 = __expf(ad[0]-am0), e1 = __expf(ad[1]-am0);
        float e2 = __expf(ad[2]-am1), e3 = __expf(ad[3]-am1);
        float x0 = hasx ? __expf(adx[0]-am0) : 0.f, x1 = hasx ? __expf(adx[1]-am0) : 0.f;
        float x2 = hasx ? __expf(adx[2]-am1) : 0.f, x3 = hasx ? __expf(adx[3]-am1) : 0.f;
        float t0 = e0 + e1 + x0 + x1, t1 = e2 + e3 + x2 + x3;
        t0 += __shfl_xor_sync(0xffffffffu, t0, 1);
        t0 += __shfl_xor_sync(0xffffffffu, t0, 2);
        t1 += __shfl_xor_sync(0xffffffffu, t1, 1);
        t1 += __shfl_xor_sync(0xffffffffu, t1, 2);
        float c0 = g1t / t0, c1 = g1t / t1;
        __half2 a0h = __floats2half2_rn(e0*c0, e1*c0);
        __half2 a1h = __floats2half2_rn(e2*c1, e3*c1);
        __half2 a2h = __floats2half2_rn(x0*c0, x1*c0);
        __half2 a3h = __floats2half2_rn(x2*c1, x3*c1);
        uint32_t ap[4] = { *(uint32_t*)&a0h, *(uint32_t*)&a1h,
                           *(uint32_t*)&a2h, *(uint32_t*)&a3h };
        uint32_t vb[8][4];
        #pragma unroll
        for (int nj = 0; nj < 8; nj++)
            LDSM4(vb[nj], sb + FA_VA_OFF + (nj*16 + rsel)*48 + csel*16);
        #pragma unroll
        for (int ni = 0; ni < 16; ni++)
            mma16(oacc[ni], ap, vb[ni>>1][ni&1], vb[ni>>1][(ni&1)+2]);
    }

    // store O (fp16)
    long long rbase = (long long)(b*SEQL + m0 + warp*16);
    #pragma unroll
    for (int ni = 0; ni < 16; ni++) {
        int col = h*HDIM + ni*8 + ec;
        *(__half2*)(g_Oh + (rbase + er)*DIMM + col) =
            __floats2half2_rn(oacc[ni][0], oacc[ni][1]);
        *(__half2*)(g_Oh + (rbase + er + 8)*DIMM + col) =
            __floats2half2_rn(oacc[ni][2], oacc[ni][3]);
    }
}

// ---------------- fp32 -> fp16 conversion, 4 float4 per thread (MLP=4) ------
__global__ void f2h_kernel(const float* __restrict__ in, __half* __restrict__ out) {
    int base = blockIdx.x * 1024 + threadIdx.x;
    float4 v[4];
    #pragma unroll
    for (int j = 0; j < 4; j++) v[j] = ((const float4*)in)[base + j*256];
    #pragma unroll
    for (int j = 0; j < 4; j++) {
        int i = base + j*256;
        ((__half2*)out)[2*i]   = __floats2half2_rn(v[j].x, v[j].y);
        ((__half2*)out)[2*i+1] = __floats2half2_rn(v[j].z, v[j].w);
    }
}

__global__ void f2h4_kernel(const float* __restrict__ w0, const float* __restrict__ w1,
                            const float* __restrict__ w2, const float* __restrict__ w3,
                            __half* __restrict__ wh, __half* __restrict__ woh) {
    const float* in;  __half* out;
    switch (blockIdx.y) {
        case 0: in = w0; out = wh; break;
        case 1: in = w1; out = wh + (long long)DIMM*DIMM; break;
        case 2: in = w2; out = wh + 2LL*DIMM*DIMM; break;
        default: in = w3; out = woh; break;
    }
    int base = blockIdx.x * 1024 + threadIdx.x;
    float4 v[4];
    #pragma unroll
    for (int j = 0; j < 4; j++) v[j] = ((const float4*)in)[base + j*256];
    #pragma unroll
    for (int j = 0; j < 4; j++) {
        int i = base + j*256;
        ((__half2*)out)[2*i]   = __floats2half2_rn(v[j].x, v[j].y);
        ((__half2*)out)[2*i+1] = __floats2half2_rn(v[j].z, v[j].w);
    }
}

// ---------------- adapter rows -> xh rows 2048..2175 ------------------------
__global__ void adapter_fill_kernel(const float* __restrict__ adp) {
    int i = blockIdx.x * 256 + threadIdx.x;
    int row = i >> 8;
    int c8 = (i & 255) * 8;
    __half h[8];
    if (row < ALEN) {
        #pragma unroll
        for (int j = 0; j < 8; j++) h[j] = __float2half(adp[row*DIMM + c8 + j]);
    } else {
        #pragma unroll
        for (int j = 0; j < 8; j++) h[j] = __float2half(0.f);
    }
    *(uint4*)(g_xh + (long long)(BS*SEQL + row)*DIMM + c8) = *(uint4*)h;
}

// ---------------- transposed [adapter|values|pad] V (fp16 in) ---------------
__global__ void transpose_v_kernel()
{
    __shared__ float tile[32][33];
    int z = blockIdx.z;
    int b = z >> 4, h = z & 15;
    int kt = blockIdx.x * 32, dt = blockIdx.y * 32;
    int tx = threadIdx.x, ty = threadIdx.y;
    #pragma unroll
    for (int j = 0; j < 4; j++) {
        int k = kt + ty + 8*j;
        int d = dt + tx;
        float v = 0.f;
        if (k < ALEN) v = __half2float(g_Vh[(long long)(BS*SEQL + k)*DIMM + h*HDIM + d]);
        else if (k < ALEN + SEQL)
            v = __half2float(g_Vh[((long long)(b * SEQL + k - ALEN)) * DIMM + h * HDIM + d]);
        tile[ty + 8*j][tx] = v;
    }
    __syncthreads();
    #pragma unroll
    for (int j = 0; j < 4; j++) {
        int d = dt + ty + 8*j;
        g_Vth[((long long)z * HDIM + d) * KCAT + kt + tx] = __float2half(tile[tx][ty + 8*j]);
    }
}

// ---------------- launch -----------------------------------------------------
extern "C" void kernel_launch(void* const* d_in, const int* in_sizes, int n_in,
                              void* d_out, int out_size)
{
    const float* x   = (const float*)d_in[0];
    const float* adp = (const float*)d_in[1];
    /* d_in[2] = mask: equivalent to hard causal mask, recomputed on device */
    const float* fc  = (const float*)d_in[3];
    const float* fs  = (const float*)d_in[4];
    const float* wq  = (const float*)d_in[5];
    const float* wk  = (const float*)d_in[6];
    const float* wv  = (const float*)d_in[7];
    const float* wo  = (const float*)d_in[8];
    const float* g1  = (const float*)d_in[9];
    const float* g2  = (const float*)d_in[10];
    const int*   vsp = (const int*)d_in[11];
    float* out = (float*)d_out;

    __half *xh, *wh, *woh, *Ohp;
    cudaGetSymbolAddress((void**)&xh,  g_xh);
    cudaGetSymbolAddress((void**)&wh,  g_wh);
    cudaGetSymbolAddress((void**)&woh, g_woh);
    cudaGetSymbolAddress((void**)&Ohp, g_Oh);

    cudaFuncSetAttribute((const void*)hgemm<float,true>,  cudaFuncAttributeMaxDynamicSharedMemorySize, HG_SMEM);
    cudaFuncSetAttribute((const void*)hgemm<float,false>, cudaFuncAttributeMaxDynamicSharedMemorySize, HG_SMEM);
    cudaFuncSetAttribute((const void*)flash_kernel, cudaFuncAttributeMaxDynamicSharedMemorySize, FA_SMEM);

    f2h_kernel<<<BS*SEQL*DIMM/4096, 256>>>(x, xh);
    f2h4_kernel<<<dim3(DIMM*DIMM/4096, 4), 256>>>(wq, wk, wv, wo, wh, woh);
    adapter_fill_kernel<<<128, 256>>>(adp);

    // QKV projections fused (M=2176 incl. adapter rows), rope/scatter epilogue
    hgemm<float,true><<<dim3(DIMM/128, MPAD/128, 3), 256, HG_SMEM>>>(
        xh, wh, (float*)Ohp /*unused*/, DIMM, DIMM, DIMM, DIMM,
        (long long)DIMM*DIMM, 0, 3, fc, fs);

    transpose_v_kernel<<<dim3(KCAT/32, HDIM/32, BS*NHEADS), dim3(32, 8)>>>();

    // fused attention: QK + two-segment softmax + PV
    flash_kernel<<<512, 128, FA_SMEM>>>(g1, g2, vsp);

    // output projection: fp32 out to d_out
    hgemm<float,false><<<dim3(DIMM/128, (BS*SEQL)/128, 1), 256, HG_SMEM>>>(
        Ohp, woh, out, DIMM, DIMM, DIMM, DIMM, 0, 0, 1, nullptr, nullptr);
}

// round 15
// speedup vs baseline: 1.5381x; 1.0028x over previous
#include <cuda_runtime.h>
#include <cuda_fp16.h>
#include <math.h>
#include <stdint.h>

#define DIMM   2048
#define NHEADS 16
#define HDIM   128
#define SEQL   1024
#define BS     2
#define ALEN   10
#define MAXF   10
#define KCAT   1152   /* 10 adapter + 1024 keys + 118 zero pad = 9*128 */
#define MPAD   (BS*SEQL + 128)   /* 2176: x rows + adapter row tile */
#define QSCALE 0.08838834764831843f

// ---------------- scratch (device globals; no allocation allowed) ----------
__device__ __half g_xh [MPAD*DIMM];          // x (2048) | adapter (10) | zeros
__device__ __half g_wh [3*DIMM*DIMM];        // wq|wk|wv fp16 contiguous
__device__ __half g_woh[DIMM*DIMM];
__device__ __half g_Qh [BS*SEQL*DIMM];       // roped + pre-scaled Q
__device__ __half g_Vh [MPAD*DIMM];          // V fp16 (incl. adapter rows)
__device__ __half g_Kch[BS*NHEADS*KCAT*HDIM];
__device__ __half g_Vth[BS*NHEADS*HDIM*KCAT];   // V transposed: [z][d][k]
__device__ __half g_Oh [BS*SEQL*DIMM];

// ---------------- PTX helpers ----------------------------------------------
__device__ __forceinline__ uint32_t smem_to_u32(const void* p) {
    uint32_t a;
    asm("{ .reg .u64 t; cvta.to.shared.u64 t, %1; cvt.u32.u64 %0, t; }" : "=r"(a) : "l"(p));
    return a;
}
#define CP16(dst, src) \
    asm volatile("cp.async.cg.shared.global [%0], [%1], 16;" :: "r"(dst), "l"(src))
#define CP_COMMIT() asm volatile("cp.async.commit_group;" ::: "memory")
#define CP_WAIT0()  asm volatile("cp.async.wait_group 0;" ::: "memory")
#define CP_WAIT1()  asm volatile("cp.async.wait_group 1;" ::: "memory")
#define CP_WAIT2()  asm volatile("cp.async.wait_group 2;" ::: "memory")

#define LDSM4(r, a) \
    asm volatile("ldmatrix.sync.aligned.m8n8.x4.shared.b16 {%0,%1,%2,%3},[%4];" \
        : "=r"((r)[0]), "=r"((r)[1]), "=r"((r)[2]), "=r"((r)[3]) : "r"(a))

__device__ __forceinline__ void mma16(float* c, const uint32_t* a, uint32_t b0, uint32_t b1) {
    asm volatile(
        "mma.sync.aligned.m16n8k16.row.col.f32.f16.f16.f32 "
        "{%0,%1,%2,%3},{%4,%5,%6,%7},{%8,%9},{%0,%1,%2,%3};"
        : "+f"(c[0]), "+f"(c[1]), "+f"(c[2]), "+f"(c[3])
        : "r"(a[0]), "r"(a[1]), "r"(a[2]), "r"(a[3]), "r"(b0), "r"(b1));
}

// ---------------- fp16 tensor-core batched GEMM: C = A @ B^T ----------------
// CTA tile 128x128, 8 warps (2m x 4n), warp tile 64x32, BK=32, 4-stage cp.async.
// Mainloop unrolled x4 so stage indices & copy addresses constant-fold.
#define HG_STAGE 20480
#define HG_SMEM  81920

template <typename OutT, bool FUSE>
__global__ __launch_bounds__(256, 2) void hgemm(
    const __half* __restrict__ A, const __half* __restrict__ B, OutT* __restrict__ C,
    int K, int lda, int ldb, int ldc,
    long long bSh, long long cSh, int nh,
    const float* __restrict__ fc, const float* __restrict__ fs)
{
    const int m0 = blockIdx.y * 128, n0 = blockIdx.x * 128;
    extern __shared__ char smem[];
    const uint32_t sb = smem_to_u32(smem);
    int zh = blockIdx.z % nh;
    B += zh*bSh;
    C += zh*cSh;

    const int tid = threadIdx.x, lane = tid & 31, warp = tid >> 5;
    const int wm = warp & 1, wn = warp >> 1;       // warp tile 64(m) x 32(n)
    const int nch = K >> 5;

    const int crow = tid >> 1;
    const int cseg = (tid & 1) * 2;
    const __half* ag = A + (long long)(m0 + crow) * lda + cseg * 8;
    const __half* bg = B + (long long)(n0 + crow) * ldb + cseg * 8;
    const uint32_t sa = sb + crow*80 + cseg*16;
    const uint32_t sbb = sb + 10240 + crow*80 + cseg*16;

    float acc[4][4][4];
    #pragma unroll
    for (int mi = 0; mi < 4; mi++)
        #pragma unroll
        for (int ni = 0; ni < 4; ni++)
            #pragma unroll
            for (int j = 0; j < 4; j++) acc[mi][ni][j] = 0.f;

    #pragma unroll
    for (int s = 0; s < 3; s++) {
        CP16(sa  + s*HG_STAGE,      ag + s*32);
        CP16(sa  + s*HG_STAGE + 16, ag + s*32 + 8);
        CP16(sbb + s*HG_STAGE,      bg + s*32);
        CP16(sbb + s*HG_STAGE + 16, bg + s*32 + 8);
        CP_COMMIT();
    }

    const int rsel = lane & 15, csel = lane >> 4;

    #pragma unroll 4
    for (int c = 0; c < nch; c++) {
        CP_WAIT2();
        __syncthreads();

        const uint32_t abase = sb + (c & 3)*HG_STAGE + (wm*64)*80;
        const uint32_t bbase = sb + (c & 3)*HG_STAGE + 10240 + (wn*32)*80;

        uint32_t a[4][4], b[2][2][4];
        #pragma unroll
        for (int nj = 0; nj < 2; nj++)
            LDSM4(b[0][nj], bbase + (nj*16 + rsel)*80 + csel*16);
        #pragma unroll
        for (int nj = 0; nj < 2; nj++)
            LDSM4(b[1][nj], bbase + (nj*16 + rsel)*80 + 32 + csel*16);
        #pragma unroll
        for (int mi = 0; mi < 4; mi++)
            LDSM4(a[mi], abase + (mi*16 + rsel)*80 + csel*16);

        int nxt = c + 3;
        if (nxt < nch) {
            int s = nxt & 3;
            CP16(sa  + s*HG_STAGE,      ag + nxt*32);
            CP16(sa  + s*HG_STAGE + 16, ag + nxt*32 + 8);
            CP16(sbb + s*HG_STAGE,      bg + nxt*32);
            CP16(sbb + s*HG_STAGE + 16, bg + nxt*32 + 8);
        }
        CP_COMMIT();

        #pragma unroll
        for (int mi = 0; mi < 4; mi++) {
            #pragma unroll
            for (int ni = 0; ni < 4; ni++)
                mma16(acc[mi][ni], a[mi], b[0][ni>>1][ni&1], b[0][ni>>1][(ni&1)+2]);
            LDSM4(a[mi], abase + (mi*16 + rsel)*80 + 32 + csel*16);
        }
        #pragma unroll
        for (int mi = 0; mi < 4; mi++)
            #pragma unroll
            for (int ni = 0; ni < 4; ni++)
                mma16(acc[mi][ni], a[mi], b[1][ni>>1][ni&1], b[1][ni>>1][(ni&1)+2]);
    }

    const int er = lane >> 2, ec = (lane & 3) * 2;

    if (FUSE) {
        // zh: 0=Q(rope+scale->Qh), 1=K(rope+scatter->Kch), 2=V(->Vh fp16)
        #pragma unroll
        for (int mi = 0; mi < 4; mi++) {
            #pragma unroll
            for (int ni = 0; ni < 4; ni++) {
                int row = m0 + wm*64 + mi*16 + er;
                int col = n0 + wn*32 + ni*8 + ec;
                float* cc = acc[mi][ni];
                int d = col & (HDIM-1), h = col >> 7, p = d >> 1;
                #pragma unroll
                for (int rr = 0; rr < 2; rr++) {
                    int r_ = row + rr*8;
                    float vx = cc[rr*2], vy = cc[rr*2 + 1];
                    if (zh == 2) {
                        *(__half2*)(g_Vh + (long long)r_*DIMM + col) = __floats2half2_rn(vx, vy);
                    } else if (r_ < BS*SEQL) {
                        int q = r_ & (SEQL-1);
                        float cv = fc[q*64 + p], sv = fs[q*64 + p];
                        float ox = vx*cv - vy*sv, oy = vx*sv + vy*cv;
                        if (zh == 0) {
                            *(__half2*)(g_Qh + (long long)r_*DIMM + col) =
                                __floats2half2_rn(ox*QSCALE, oy*QSCALE);
                        } else {
                            int b = r_ >> 10;
                            *(__half2*)(g_Kch +
                                ((long long)(b*NHEADS + h)*KCAT + ALEN + q)*HDIM + d) =
                                __floats2half2_rn(ox, oy);
                        }
                    } else if (zh == 1 && r_ < BS*SEQL + ALEN) {
                        int j = r_ - BS*SEQL;
                        __half2 o = __floats2half2_rn(vx, vy);
                        *(__half2*)(g_Kch + ((long long)h*KCAT + j)*HDIM + d) = o;
                        *(__half2*)(g_Kch + ((long long)(NHEADS + h)*KCAT + j)*HDIM + d) = o;
                    }
                }
            }
        }
        return;
    }

    #pragma unroll
    for (int mi = 0; mi < 4; mi++) {
        #pragma unroll
        for (int ni = 0; ni < 4; ni++) {
            int row = m0 + wm*64 + mi*16 + er;
            int col = n0 + wn*32 + ni*8 + ec;
            float* cc = acc[mi][ni];
            *(float2*)((float*)C + (long long)row * ldc + col) = make_float2(cc[0], cc[1]);
            *(float2*)((float*)C + (long long)(row+8) * ldc + col) = make_float2(cc[2], cc[3]);
        }
    }
}

// ---------------- fused flash attention -------------------------------------
#define FA_PITCH  272                     /* 256B data + 16B pad */
#define FA_K_OFF  17408                   /* 64*272 Q tile */
#define FA_V_OFF  (17408 + 34816)
#define FA_VA_OFF (FA_V_OFF + 34816)      /* 128 x 48B adapter-V block */
#define FA_SMEM   (FA_VA_OFF + 6144)      /* 93184 */

__global__ __launch_bounds__(128, 2) void flash_kernel(
    const float* __restrict__ gate1, const float* __restrict__ gate2,
    const int* __restrict__ vsp)
{
    extern __shared__ char smem[];
    const uint32_t sb = smem_to_u32(smem);
    const int bx = blockIdx.x;
    const int z = bx & 31;
    const int mi = 15 - (bx >> 5);        // heavy tiles first (LPT)
    const int m0 = mi * 64;
    const int b = z >> 4, h = z & 15;
    const int tid = threadIdx.x, lane = tid & 31, warp = tid >> 5;
    const int rsel = lane & 15, csel = lane >> 4;
    const int er = lane >> 2, ec = (lane & 3) * 2;
    const int vs = *vsp;
    const float g2 = gate2[h];

    const __half* Qg = g_Qh + ((long long)(b*SEQL + m0))*DIMM + h*HDIM;
    const __half* Kg = g_Kch + (long long)z*KCAT*HDIM;
    const __half* Vg = g_Vth + (long long)z*HDIM*KCAT;

    {
        int row = tid >> 1, seg = tid & 1;
        const __half* src = Qg + (long long)row*DIMM + seg*64;
        uint32_t dst = sb + row*FA_PITCH + seg*128;
        #pragma unroll
        for (int i = 0; i < 8; i++) CP16(dst + i*16, src + i*8);
    }
    {
        const __half* src = Vg + (long long)tid*KCAT;
        uint32_t dst = sb + FA_VA_OFF + tid*48;
        CP16(dst, src); CP16(dst + 16, src + 8);
    }
    {
        const __half* ks = Kg + tid*HDIM;
        uint32_t kd = sb + FA_K_OFF + tid*FA_PITCH;
        #pragma unroll
        for (int i = 0; i < 16; i++) CP16(kd + i*16, ks + i*8);
        const __half* vsrc = Vg + (long long)tid*KCAT;
        uint32_t vd = sb + FA_V_OFF + tid*FA_PITCH;
        #pragma unroll
        for (int i = 0; i < 16; i++) CP16(vd + i*16, vsrc + i*8);
    }
    CP_COMMIT();

    const int q0 = m0 + warp*16 + er, q1 = q0 + 8;
    const bool grow0 = q0 >= vs + MAXF, grow1 = q1 >= vs + MAXF;

    float oacc[16][4];
    #pragma unroll
    for (int n = 0; n < 16; n++)
        oacc[n][0] = oacc[n][1] = oacc[n][2] = oacc[n][3] = 0.f;
    float m0r = -1e30f, m1r = -1e30f, l0 = 0.f, l1 = 0.f;
    float ad[4], adx[4];

    const int nkt = (m0 + 73)/128 + 1;

    for (int kt = 0; kt < nkt; kt++) {
        if (kt == 0) CP_WAIT0(); else CP_WAIT1();
        __syncthreads();

        float sacc[16][4];
        #pragma unroll
        for (int n = 0; n < 16; n++)
            sacc[n][0] = sacc[n][1] = sacc[n][2] = sacc[n][3] = 0.f;

        #pragma unroll
        for (int kk = 0; kk < 8; kk++) {
            uint32_t a[4], bf[8][4];
            LDSM4(a, sb + (warp*16 + rsel)*FA_PITCH + kk*32 + csel*16);
            #pragma unroll
            for (int nj = 0; nj < 8; nj++)
                LDSM4(bf[nj], sb + FA_K_OFF + (nj*16 + rsel)*FA_PITCH + kk*32 + csel*16);
            #pragma unroll
            for (int ni = 0; ni < 16; ni++)
                mma16(sacc[ni], a, bf[ni>>1][ni&1], bf[ni>>1][(ni&1)+2]);
        }
        __syncthreads();
        if (kt + 1 < nkt) {
            const __half* src = Kg + (long long)(kt+1)*128*HDIM + tid*HDIM;
            uint32_t dst = sb + FA_K_OFF + tid*FA_PITCH;
            #pragma unroll
            for (int i = 0; i < 16; i++) CP16(dst + i*16, src + i*8);
        }
        CP_COMMIT();

        if (kt == 0) {
            #pragma unroll
            for (int j = 0; j < 4; j++) { ad[j] = sacc[0][j]; adx[j] = sacc[1][j]; }
        }

        float mx0 = -1e30f, mx1 = -1e30f;
        #pragma unroll
        for (int ni = 0; ni < 16; ni++) {
            #pragma unroll
            for (int j = 0; j < 4; j++) {
                int kkey = kt*128 + ni*8 + ec + (j & 1) - ALEN;
                int q = (j < 2) ? q0 : q1;
                bool gr = (j < 2) ? grow0 : grow1;
                float s = sacc[ni][j];
                bool val = (kkey >= 0) && (kkey <= q);
                if (val && gr && kkey >= vs && kkey < vs + MAXF) s += g2;
                s = val ? s : -1e30f;
                sacc[ni][j] = s;
                if (j < 2) mx0 = fmaxf(mx0, s); else mx1 = fmaxf(mx1, s);
            }
        }
        mx0 = fmaxf(mx0, __shfl_xor_sync(0xffffffffu, mx0, 1));
        mx0 = fmaxf(mx0, __shfl_xor_sync(0xffffffffu, mx0, 2));
        mx1 = fmaxf(mx1, __shfl_xor_sync(0xffffffffu, mx1, 1));
        mx1 = fmaxf(mx1, __shfl_xor_sync(0xffffffffu, mx1, 2));
        float nm0 = fmaxf(m0r, mx0), nm1 = fmaxf(m1r, mx1);
        float sc0 = __expf(m0r - nm0), sc1 = __expf(m1r - nm1);
        m0r = nm0; m1r = nm1;
        l0 *= sc0; l1 *= sc1;
        #pragma unroll
        for (int n = 0; n < 16; n++) {
            oacc[n][0] *= sc0; oacc[n][1] *= sc0;
            oacc[n][2] *= sc1; oacc[n][3] *= sc1;
        }

        uint32_t pu[16][2];
        float s0 = 0.f, s1 = 0.f;
        #pragma unroll
        for (int ni = 0; ni < 16; ni++) {
            float p0 = __expf(sacc[ni][0] - m0r);
            float p1 = __expf(sacc[ni][1] - m0r);
            float p2 = __expf(sacc[ni][2] - m1r);
            float p3 = __expf(sacc[ni][3] - m1r);
            s0 += p0 + p1; s1 += p2 + p3;
            __half2 h0 = __floats2half2_rn(p0, p1);
            __half2 h1 = __floats2half2_rn(p2, p3);
            pu[ni][0] = *(uint32_t*)&h0;
            pu[ni][1] = *(uint32_t*)&h1;
        }
        s0 += __shfl_xor_sync(0xffffffffu, s0, 1);
        s0 += __shfl_xor_sync(0xffffffffu, s0, 2);
        s1 += __shfl_xor_sync(0xffffffffu, s1, 1);
        s1 += __shfl_xor_sync(0xffffffffu, s1, 2);
        l0 += s0; l1 += s1;

        CP_WAIT1();
        __syncthreads();

        #pragma unroll
        for (int kk = 0; kk < 8; kk++) {
            uint32_t vb[8][4];
            #pragma unroll
            for (int nj = 0; nj < 8; nj++)
                LDSM4(vb[nj], sb + FA_V_OFF + (nj*16 + rsel)*FA_PITCH + kk*32 + csel*16);
            uint32_t ap[4] = { pu[2*kk][0], pu[2*kk][1], pu[2*kk+1][0], pu[2*kk+1][1] };
            #pragma unroll
            for (int ni = 0; ni < 16; ni++)
                mma16(oacc[ni], ap, vb[ni>>1][ni&1], vb[ni>>1][(ni&1)+2]);
        }
        __syncthreads();
        if (kt + 1 < nkt) {
            const __half* src = Vg + (long long)tid*KCAT + (kt+1)*128;
            uint32_t dst = sb + FA_V_OFF + tid*FA_PITCH;
            #pragma unroll
            for (int i = 0; i < 16; i++) CP16(dst + i*16, src + i*8);
        }
        CP_COMMIT();
    }

    float inv0 = 1.f / l0, inv1 = 1.f / l1;
    #pragma unroll
    for (int n = 0; n < 16; n++) {
        oacc[n][0] *= inv0; oacc[n][1] *= inv0;
        oacc[n][2] *= inv1; oacc[n][3] *= inv1;
    }

    {
        float g1t = tanhf(gate1[h]);
        bool hasx = (ec == 0);
        float am0 = fmaxf(ad[0], ad[1]);
        float am1 = fmaxf(ad[2], ad[3]);
        if (hasx) { am0 = fmaxf(am0, fmaxf(adx[0], adx[1]));
                    am1 = fmaxf(am1, fmaxf(adx[2], adx[3])); }
        am0 = fmaxf(am0, __shfl_xor_sync(0xffffffffu, am0, 1));
        am0 = fmaxf(am0, __shfl_xor_sync(0xffffffffu, am0, 2));
        am1 = fmaxf(am1, __shfl_xor_sync(0xffffffffu, am1, 1));
        am1 = fmaxf(am1, __shfl_xor_sync(0xffffffffu, am1, 2));
        float e0 = __expf(ad[0]-am0), e1 = __expf(ad[1]-am0);
        float e2 = __expf(ad[2]-am1), e3 = __expf(ad[3]-am1);
        float x0 = hasx ? __expf(adx[0]-am0) : 0.f, x1 = hasx ? __expf(adx[1]-am0) : 0.f;
        float x2 = hasx ? __expf(adx[2]-am1) : 0.f, x3 = hasx ? __expf(adx[3]-am1) : 0.f;
        float t0 = e0 + e1 + x0 + x1, t1 = e2 + e3 + x2 + x3;
        t0 += __shfl_xor_sync(0xffffffffu, t0, 1);
        t0 += __shfl_xor_sync(0xffffffffu, t0, 2);
        t1 += __shfl_xor_sync(0xffffffffu, t1, 1);
        t1 += __shfl_xor_sync(0xffffffffu, t1, 2);
        float c0 = g1t / t0, c1 = g1t / t1;
        __half2 a0h = __floats2half2_rn(e0*c0, e1*c0);
        __half2 a1h = __floats2half2_rn(e2*c1, e3*c1);
        __half2 a2h = __floats2half2_rn(x0*c0, x1*c0);
        __half2 a3h = __floats2half2_rn(x2*c1, x3*c1);
        uint32_t ap[4] = { *(uint32_t*)&a0h, *(uint32_t*)&a1h,
                           *(uint32_t*)&a2h, *(uint32_t*)&a3h };
        uint32_t vb[8][4];
        #pragma unroll
        for (int nj = 0; nj < 8; nj++)
            LDSM4(vb[nj], sb + FA_VA_OFF + (nj*16 + rsel)*48 + csel*16);
        #pragma unroll
        for (int ni = 0; ni < 16; ni++)
            mma16(oacc[ni], ap, vb[ni>>1][ni&1], vb[ni>>1][(ni&1)+2]);
    }

    long long rbase = (long long)(b*SEQL + m0 + warp*16);
    #pragma unroll
    for (int ni = 0; ni < 16; ni++) {
        int col = h*HDIM + ni*8 + ec;
        *(__half2*)(g_Oh + (rbase + er)*DIMM + col) =
            __floats2half2_rn(oacc[ni][0], oacc[ni][1]);
        *(__half2*)(g_Oh + (rbase + er + 8)*DIMM + col) =
            __floats2half2_rn(oacc[ni][2], oacc[ni][3]);
    }
}

// ---------------- fp32 -> fp16 conversion, 4 float4 per thread (MLP=4) ------
__global__ void f2h_kernel(const float* __restrict__ in, __half* __restrict__ out) {
    int base = blockIdx.x * 1024 + threadIdx.x;
    float4 v[4];
    #pragma unroll
    for (int j = 0; j < 4; j++) v[j] = ((const float4*)in)[base + j*256];
    #pragma unroll
    for (int j = 0; j < 4; j++) {
        int i = base + j*256;
        ((__half2*)out)[2*i]   = __floats2half2_rn(v[j].x, v[j].y);
        ((__half2*)out)[2*i+1] = __floats2half2_rn(v[j].z, v[j].w);
    }
}

__global__ void f2h4_kernel(const float* __restrict__ w0, const float* __restrict__ w1,
                            const float* __restrict__ w2, const float* __restrict__ w3,
                            __half* __restrict__ wh, __half* __restrict__ woh) {
    const float* in;  __half* out;
    switch (blockIdx.y) {
        case 0: in = w0; out = wh; break;
        case 1: in = w1; out = wh + (long long)DIMM*DIMM; break;
        case 2: in = w2; out = wh + 2LL*DIMM*DIMM; break;
        default: in = w3; out = woh; break;
    }
    int base = blockIdx.x * 1024 + threadIdx.x;
    float4 v[4];
    #pragma unroll
    for (int j = 0; j < 4; j++) v[j] = ((const float4*)in)[base + j*256];
    #pragma unroll
    for (int j = 0; j < 4; j++) {
        int i = base + j*256;
        ((__half2*)out)[2*i]   = __floats2half2_rn(v[j].x, v[j].y);
        ((__half2*)out)[2*i+1] = __floats2half2_rn(v[j].z, v[j].w);
    }
}

// ---------------- adapter rows -> xh rows 2048..2175 ------------------------
__global__ void adapter_fill_kernel(const float* __restrict__ adp) {
    int i = blockIdx.x * 256 + threadIdx.x;
    int row = i >> 8;
    int c8 = (i & 255) * 8;
    __half h[8];
    if (row < ALEN) {
        #pragma unroll
        for (int j = 0; j < 8; j++) h[j] = __float2half(adp[row*DIMM + c8 + j]);
    } else {
        #pragma unroll
        for (int j = 0; j < 8; j++) h[j] = __float2half(0.f);
    }
    *(uint4*)(g_xh + (long long)(BS*SEQL + row)*DIMM + c8) = *(uint4*)h;
}

// ---------------- transposed [adapter|values|pad] V (fp16 in) ---------------
__global__ void transpose_v_kernel()
{
    __shared__ float tile[32][33];
    int z = blockIdx.z;
    int b = z >> 4, h = z & 15;
    int kt = blockIdx.x * 32, dt = blockIdx.y * 32;
    int tx = threadIdx.x, ty = threadIdx.y;
    #pragma unroll
    for (int j = 0; j < 4; j++) {
        int k = kt + ty + 8*j;
        int d = dt + tx;
        float v = 0.f;
        if (k < ALEN) v = __half2float(g_Vh[(long long)(BS*SEQL + k)*DIMM + h*HDIM + d]);
        else if (k < ALEN + SEQL)
            v = __half2float(g_Vh[((long long)(b * SEQL + k - ALEN)) * DIMM + h * HDIM + d]);
        tile[ty + 8*j][tx] = v;
    }
    __syncthreads();
    #pragma unroll
    for (int j = 0; j < 4; j++) {
        int d = dt + ty + 8*j;
        g_Vth[((long long)z * HDIM + d) * KCAT + kt + tx] = __float2half(tile[tx][ty + 8*j]);
    }
}

// ---------------- launch -----------------------------------------------------
extern "C" void kernel_launch(void* const* d_in, const int* in_sizes, int n_in,
                              void* d_out, int out_size)
{
    const float* x   = (const float*)d_in[0];
    const float* adp = (const float*)d_in[1];
    /* d_in[2] = mask: equivalent to hard causal mask, recomputed on device */
    const float* fc  = (const float*)d_in[3];
    const float* fs  = (const float*)d_in[4];
    const float* wq  = (const float*)d_in[5];
    const float* wk  = (const float*)d_in[6];
    const float* wv  = (const float*)d_in[7];
    const float* wo  = (const float*)d_in[8];
    const float* g1  = (const float*)d_in[9];
    const float* g2  = (const float*)d_in[10];
    const int*   vsp = (const int*)d_in[11];
    float* out = (float*)d_out;

    __half *xh, *wh, *woh, *Ohp;
    cudaGetSymbolAddress((void**)&xh,  g_xh);
    cudaGetSymbolAddress((void**)&wh,  g_wh);
    cudaGetSymbolAddress((void**)&woh, g_woh);
    cudaGetSymbolAddress((void**)&Ohp, g_Oh);

    cudaFuncSetAttribute((const void*)hgemm<float,true>,  cudaFuncAttributeMaxDynamicSharedMemorySize, HG_SMEM);
    cudaFuncSetAttribute((const void*)hgemm<float,false>, cudaFuncAttributeMaxDynamicSharedMemorySize, HG_SMEM);
    cudaFuncSetAttribute((const void*)flash_kernel, cudaFuncAttributeMaxDynamicSharedMemorySize, FA_SMEM);

    f2h_kernel<<<BS*SEQL*DIMM/4096, 256>>>(x, xh);
    f2h4_kernel<<<dim3(DIMM*DIMM/4096, 4), 256>>>(wq, wk, wv, wo, wh, woh);
    adapter_fill_kernel<<<128, 256>>>(adp);

    // QKV projections fused (M=2176 incl. adapter rows), rope/scatter epilogue
    hgemm<float,true><<<dim3(DIMM/128, MPAD/128, 3), 256, HG_SMEM>>>(
        xh, wh, (float*)Ohp /*unused*/, DIMM, DIMM, DIMM, DIMM,
        (long long)DIMM*DIMM, 0, 3, fc, fs);

    transpose_v_kernel<<<dim3(KCAT/32, HDIM/32, BS*NHEADS), dim3(32, 8)>>>();

    // fused attention: QK + two-segment softmax + PV
    flash_kernel<<<512, 128, FA_SMEM>>>(g1, g2, vsp);

    // output projection: fp32 out to d_out
    hgemm<float,false><<<dim3(DIMM/128, (BS*SEQL)/128, 1), 256, HG_SMEM>>>(
        Ohp, woh, out, DIMM, DIMM, DIMM, DIMM, 0, 0, 1, nullptr, nullptr);
}